// round 13
// baseline (speedup 1.0000x reference)
#include <cuda_runtime.h>
#include <cuda_bf16.h>
#include <math.h>

#define NN 50000
#define NE 400000
#define HID 128
#define FEAT 320
#define TEDGE 128
#define TN 64
#define NTHREADS 512
#define NBLOCKS 148

typedef unsigned long long u64;
typedef unsigned int u32;

// ---------------- smem byte offsets ----------------
#define OFF_WC_HI   0         // WC^T [192n][128k] bf16, 256B rows, swizzled
#define OFF_WC_LO   49152
#define OFF_W2_HI   98304     // W2^T [128c][64j] bf16, 128B rows
#define OFF_W2_LO   114688
#define OFF_NF_HI   131072    // nf [128e][128k] bf16, 256B rows
#define OFF_NF_LO   163840
#define OFF_H_HI    131072    // h [128e][64j] overlays NF_HI (dead after MMA C)
#define OFF_H_LO    147456
#define OFF_RAD     196608    // 128*9 floats
#define OFF_Y1      201216    // 128*4 floats
#define OFF_W1S     203264    // 512 floats
#define OFF_SND     205312
#define OFF_RCV     205824
#define SMEM_BYTES  206336

__device__ float g_A[(size_t)NN * FEAT];
__device__ unsigned int g_arrive;
__device__ unsigned int g_depart;

__device__ __forceinline__ u64 pack2(float a, float b) {
    u64 r; asm("mov.b64 %0, {%1,%2};" : "=l"(r) : "f"(a), "f"(b)); return r;
}
__device__ __forceinline__ void unpack2(u64 v, float& a, float& b) {
    asm("mov.b64 {%0,%1}, %2;" : "=f"(a), "=f"(b) : "l"(v));
}
__device__ __forceinline__ void fma2(u64& d, u64 a, u64 b) {
    asm("fma.rn.f32x2 %0, %1, %2, %0;" : "+l"(d) : "l"(a), "l"(b));
}
__device__ __forceinline__ void red4(float* p, float a, float b, float c, float d) {
    asm volatile("red.global.add.v4.f32 [%0], {%1,%2,%3,%4};"
                 :: "l"(p), "f"(a), "f"(b), "f"(c), "f"(d) : "memory");
}
__device__ __forceinline__ void red2(float* p, float a, float b) {
    asm volatile("red.global.add.v2.f32 [%0], {%1,%2};"
                 :: "l"(p), "f"(a), "f"(b) : "memory");
}
__device__ __forceinline__ u32 smem_u32_of(const void* p) {
    u32 a; asm("{ .reg .u64 t; cvta.to.shared.u64 t, %1; cvt.u32.u64 %0, t; }"
               : "=r"(a) : "l"(p));
    return a;
}
__device__ __forceinline__ u32 prmt7632(u32 a, u32 b) {
    u32 d; asm("prmt.b32 %0,%1,%2,0x7632;" : "=r"(d) : "r"(a), "r"(b)); return d;
}
__device__ __forceinline__ u32 cvt_bf2(float lo, float hi) {
    u32 d; asm("cvt.rn.bf16x2.f32 %0, %1, %2;" : "=r"(d) : "f"(hi), "f"(lo)); return d;
}
__device__ __forceinline__ void split2(float a, float b, u32& h, u32& l) {
    u32 au = __float_as_uint(a), bu = __float_as_uint(b);
    h = prmt7632(au, bu);
    l = cvt_bf2(a - __uint_as_float(au & 0xFFFF0000u),
                b - __uint_as_float(bu & 0xFFFF0000u));
}
__device__ __forceinline__ u32 swz(int row, int granule, int stride) {
    return (u32)(row * stride + (((granule ^ (row & 7)) << 4)));
}
__device__ __forceinline__ void lda(u32* f, u32 base, int R, int g0, int lane, int stride) {
    int row = R + (lane & 15);
    int g = g0 + (lane >> 4);
    u32 addr = base + swz(row, g, stride);
    asm volatile("ldmatrix.sync.aligned.m8n8.x4.shared.b16 {%0,%1,%2,%3}, [%4];"
                 : "=r"(f[0]), "=r"(f[1]), "=r"(f[2]), "=r"(f[3]) : "r"(addr));
}
__device__ __forceinline__ void ldb(u32* f, u32 base, int N0, int g0, int lane, int stride) {
    int n = N0 + (lane & 7) + ((lane >> 4) << 3);
    int g = g0 + ((lane >> 3) & 1);
    u32 addr = base + swz(n, g, stride);
    asm volatile("ldmatrix.sync.aligned.m8n8.x4.shared.b16 {%0,%1,%2,%3}, [%4];"
                 : "=r"(f[0]), "=r"(f[1]), "=r"(f[2]), "=r"(f[3]) : "r"(addr));
}
__device__ __forceinline__ void mma16816(float* d, const u32* a, u32 b0, u32 b1) {
    asm volatile("mma.sync.aligned.m16n8k16.row.col.f32.bf16.bf16.f32 "
                 "{%0,%1,%2,%3}, {%4,%5,%6,%7}, {%8,%9}, {%0,%1,%2,%3};"
                 : "+f"(d[0]), "+f"(d[1]), "+f"(d[2]), "+f"(d[3])
                 : "r"(a[0]), "r"(a[1]), "r"(a[2]), "r"(a[3]), "r"(b0), "r"(b1));
}

__global__ void __launch_bounds__(NTHREADS, 1)
ace_fused_kernel(const float* __restrict__ node_attrs,
                 const int* __restrict__ edge_index,
                 const float* __restrict__ edge_vec,
                 const float* __restrict__ edge_len,
                 const float* __restrict__ W1,
                 const float* __restrict__ W2,
                 const float* __restrict__ Wtp0,
                 const float* __restrict__ Wtp1,
                 const float* __restrict__ Wmix0,
                 float* __restrict__ out) {
    extern __shared__ char smem[];
    float* radS = (float*)(smem + OFF_RAD);
    float* y1S  = (float*)(smem + OFF_Y1);
    float* W1s  = (float*)(smem + OFF_W1S);
    int*   sndS = (int*)(smem + OFF_SND);
    int*   rcvS = (int*)(smem + OFF_RCV);

    const int tid = threadIdx.x;
    const int lane = tid & 31;
    const int wid = tid >> 5;
    const u32 sb = smem_u32_of(smem);

    // ---- stage weights: split bf16 hi/lo, swizzled ----
    for (int i = tid; i < 512; i += NTHREADS) W1s[i] = W1[i];
    for (int i = tid; i < 128 * 64; i += NTHREADS) {
        int c = i >> 6, j = i & 63;
        float v = W2[j * 128 + c];
        u32 vu = __float_as_uint(v);
        u32 off = swz(c, j >> 3, 128) + (j & 7) * 2;
        *(unsigned short*)(smem + OFF_W2_HI + off) = (unsigned short)(vu >> 16);
        *(__nv_bfloat16*)(smem + OFF_W2_LO + off) =
            __float2bfloat16(v - __uint_as_float(vu & 0xFFFF0000u));
    }
    for (int i = tid; i < 192 * 128; i += NTHREADS) {
        int n = i >> 7, k = i & 127;
        float v = (n < 128) ? Wtp0[k * 128 + n] : Wtp1[k * 64 + (n - 128)];
        u32 vu = __float_as_uint(v);
        u32 off = swz(n, k >> 3, 256) + (k & 7) * 2;
        *(unsigned short*)(smem + OFF_WC_HI + off) = (unsigned short)(vu >> 16);
        *(__nv_bfloat16*)(smem + OFF_WC_LO + off) =
            __float2bfloat16(v - __uint_as_float(vu & 0xFFFF0000u));
    }
    __syncthreads();

    const int wm = wid & 3;   // row group: 32 edges
    const int wn = wid >> 2;  // col group
    const int tq = lane & 3;  // quad thread
    const int gq = lane >> 2; // group row

    // ================= EDGE PHASE =================
    const int ntiles = NE / TEDGE;  // 3125
    for (int tile = blockIdx.x; tile < ntiles; tile += gridDim.x) {
        const int ebase = tile * TEDGE;

        // ---- Phase A: per-edge scalars ----
        if (tid < TEDGE) {
            int e = ebase + tid;
            float x = edge_len[e];
            bool valid = (x > 0.f) && (x < 5.0f);
            float pref = valid ? (0.22360679774997896f / x) : 0.f;  // sqrt(2/5)/x/sqrt(8)
#pragma unroll
            for (int r = 0; r < 8; r++)
                radS[tid * 9 + r] = pref * sinf((float)(r + 1) * 0.6283185307179586f * x);
            float vx = edge_vec[e * 3 + 0];
            float vy = edge_vec[e * 3 + 1];
            float vz = edge_vec[e * 3 + 2];
            float rn = rsqrtf(vx * vx + vy * vy + vz * vz) * 1.7320508075688772f;
            y1S[tid * 4 + 0] = vy * rn;
            y1S[tid * 4 + 1] = vz * rn;
            y1S[tid * 4 + 2] = vx * rn;
            sndS[tid] = edge_index[e];
            rcvS[tid] = edge_index[NE + e];
        }
        __syncthreads();

        // ---- prefetch node_attrs gather (overlaps Phase B + MMA C) ----
        float2 atv[2][2][4];
#pragma unroll
        for (int mt = 0; mt < 2; mt++) {
            int r0 = wm * 32 + mt * 16 + gq;
            int s0 = sndS[r0], s1 = sndS[r0 + 8];
            const float* b0p = node_attrs + (u64)s0 * HID + wn * 32 + 2 * tq;
            const float* b1p = node_attrs + (u64)s1 * HID + wn * 32 + 2 * tq;
#pragma unroll
            for (int nt = 0; nt < 4; nt++) {
                atv[mt][0][nt] = *(const float2*)(b0p + nt * 8);
                atv[mt][1][nt] = *(const float2*)(b1p + nt * 8);
            }
        }

        // ---- Phase B: h = 0.018552463*silu(rad@W1), split bf16, swizzled ----
        {
            int e = tid >> 2;
            int j0 = (tid & 3) << 4;
            float hv[16];
#pragma unroll
            for (int i = 0; i < 16; i++) {
                float s = 0.f;
#pragma unroll
                for (int r = 0; r < 8; r++)
                    s += radS[e * 9 + r] * W1s[r * 64 + j0 + i];
                hv[i] = 0.018552463f * s / (1.f + __expf(-s));  // *SILU_2MOM*s_w2*s_tp
            }
            u32 hi[8], lo[8];
#pragma unroll
            for (int q = 0; q < 8; q++) split2(hv[2 * q], hv[2 * q + 1], hi[q], lo[q]);
            int x = j0 >> 3;
            u32 o0 = swz(e, x, 128), o1 = swz(e, x + 1, 128);
            *(uint4*)(smem + OFF_H_HI + o0) = make_uint4(hi[0], hi[1], hi[2], hi[3]);
            *(uint4*)(smem + OFF_H_HI + o1) = make_uint4(hi[4], hi[5], hi[6], hi[7]);
            *(uint4*)(smem + OFF_H_LO + o0) = make_uint4(lo[0], lo[1], lo[2], lo[3]);
            *(uint4*)(smem + OFF_H_LO + o1) = make_uint4(lo[4], lo[5], lo[6], lo[7]);
        }
        __syncthreads();

        // ---- MMA C: R_n[128e,128c] = h @ W2^T, split-bf16 3-pass ----
        float accc[2][4][4];
#pragma unroll
        for (int a = 0; a < 2; a++)
#pragma unroll
            for (int b = 0; b < 4; b++)
#pragma unroll
                for (int c = 0; c < 4; c++) accc[a][b][c] = 0.f;
#pragma unroll
        for (int k = 0; k < 4; k++) {
            int g0 = 2 * k;
            u32 ah0[4], ah1[4], al0[4], al1[4];
            lda(ah0, sb + OFF_H_HI, wm * 32,      g0, lane, 128);
            lda(ah1, sb + OFF_H_HI, wm * 32 + 16, g0, lane, 128);
            lda(al0, sb + OFF_H_LO, wm * 32,      g0, lane, 128);
            lda(al1, sb + OFF_H_LO, wm * 32 + 16, g0, lane, 128);
#pragma unroll
            for (int np = 0; np < 2; np++) {
                u32 bh[4], bl[4];
                ldb(bh, sb + OFF_W2_HI, wn * 32 + np * 16, g0, lane, 128);
                ldb(bl, sb + OFF_W2_LO, wn * 32 + np * 16, g0, lane, 128);
                mma16816(accc[0][2 * np],     ah0, bh[0], bh[1]);
                mma16816(accc[0][2 * np + 1], ah0, bh[2], bh[3]);
                mma16816(accc[1][2 * np],     ah1, bh[0], bh[1]);
                mma16816(accc[1][2 * np + 1], ah1, bh[2], bh[3]);
                mma16816(accc[0][2 * np],     al0, bh[0], bh[1]);
                mma16816(accc[0][2 * np + 1], al0, bh[2], bh[3]);
                mma16816(accc[1][2 * np],     al1, bh[0], bh[1]);
                mma16816(accc[1][2 * np + 1], al1, bh[2], bh[3]);
                mma16816(accc[0][2 * np],     ah0, bl[0], bl[1]);
                mma16816(accc[0][2 * np + 1], ah0, bl[2], bl[3]);
                mma16816(accc[1][2 * np],     ah1, bl[0], bl[1]);
                mma16816(accc[1][2 * np + 1], ah1, bl[2], bl[3]);
            }
        }

        // ---- compute nf split in regs (before barrier; h still live) ----
        u32 nfh[2][2][4], nfl[2][2][4];
#pragma unroll
        for (int mt = 0; mt < 2; mt++)
#pragma unroll
            for (int nt = 0; nt < 4; nt++) {
                split2(accc[mt][nt][0] * atv[mt][0][nt].x,
                       accc[mt][nt][1] * atv[mt][0][nt].y,
                       nfh[mt][0][nt], nfl[mt][0][nt]);
                split2(accc[mt][nt][2] * atv[mt][1][nt].x,
                       accc[mt][nt][3] * atv[mt][1][nt].y,
                       nfh[mt][1][nt], nfl[mt][1][nt]);
            }
        __syncthreads();   // all warps done reading h before nf overlays it

        // ---- store nf to smem (swizzled) ----
#pragma unroll
        for (int mt = 0; mt < 2; mt++) {
            int r0 = wm * 32 + mt * 16 + gq;
            int r1 = r0 + 8;
#pragma unroll
            for (int nt = 0; nt < 4; nt++) {
                int col = wn * 32 + nt * 8 + 2 * tq;
                u32 o0 = swz(r0, col >> 3, 256) + (col & 7) * 2;
                u32 o1 = swz(r1, col >> 3, 256) + (col & 7) * 2;
                *(u32*)(smem + OFF_NF_HI + o0) = nfh[mt][0][nt];
                *(u32*)(smem + OFF_NF_LO + o0) = nfl[mt][0][nt];
                *(u32*)(smem + OFF_NF_HI + o1) = nfh[mt][1][nt];
                *(u32*)(smem + OFF_NF_LO + o1) = nfl[mt][1][nt];
            }
        }
        __syncthreads();

        // ---- MMA D: [f0|t1][128e,192n] = nf @ WC^T, split-bf16 3-pass ----
        float accd[2][6][4];
#pragma unroll
        for (int a = 0; a < 2; a++)
#pragma unroll
            for (int b = 0; b < 6; b++)
#pragma unroll
                for (int c = 0; c < 4; c++) accd[a][b][c] = 0.f;
        const int NB = wn * 48;
#pragma unroll
        for (int k = 0; k < 8; k++) {
            int g0 = 2 * k;
            u32 ah0[4], ah1[4], al0[4], al1[4];
            lda(ah0, sb + OFF_NF_HI, wm * 32,      g0, lane, 256);
            lda(ah1, sb + OFF_NF_HI, wm * 32 + 16, g0, lane, 256);
            lda(al0, sb + OFF_NF_LO, wm * 32,      g0, lane, 256);
            lda(al1, sb + OFF_NF_LO, wm * 32 + 16, g0, lane, 256);
#pragma unroll
            for (int np = 0; np < 3; np++) {
                u32 bh[4], bl[4];
                ldb(bh, sb + OFF_WC_HI, NB + np * 16, g0, lane, 256);
                ldb(bl, sb + OFF_WC_LO, NB + np * 16, g0, lane, 256);
                mma16816(accd[0][2 * np],     ah0, bh[0], bh[1]);
                mma16816(accd[0][2 * np + 1], ah0, bh[2], bh[3]);
                mma16816(accd[1][2 * np],     ah1, bh[0], bh[1]);
                mma16816(accd[1][2 * np + 1], ah1, bh[2], bh[3]);
                mma16816(accd[0][2 * np],     al0, bh[0], bh[1]);
                mma16816(accd[0][2 * np + 1], al0, bh[2], bh[3]);
                mma16816(accd[1][2 * np],     al1, bh[0], bh[1]);
                mma16816(accd[1][2 * np + 1], al1, bh[2], bh[3]);
                mma16816(accd[0][2 * np],     ah0, bl[0], bl[1]);
                mma16816(accd[0][2 * np + 1], ah0, bl[2], bl[3]);
                mma16816(accd[1][2 * np],     ah1, bl[0], bl[1]);
                mma16816(accd[1][2 * np + 1], ah1, bl[2], bl[3]);
            }
        }

        // ---- scatter: quad-pair merge via shfl -> red4 (halves L2 requests) ----
#pragma unroll
        for (int mt = 0; mt < 2; mt++) {
            int r0 = wm * 32 + mt * 16 + gq;
            int r1 = r0 + 8;
            int myrow = (tq & 1) ? r1 : r0;
            float* gp = g_A + (u64)rcvS[myrow] * FEAT;
            float y0 = y1S[myrow * 4 + 0];
            float y1v = y1S[myrow * 4 + 1];
            float y2 = y1S[myrow * 4 + 2];
#pragma unroll
            for (int nt = 0; nt < 6; nt++) {
                u64 up0 = pack2(accd[mt][nt][0], accd[mt][nt][1]);  // row r0, own 2 cols
                u64 up1 = pack2(accd[mt][nt][2], accd[mt][nt][3]);  // row r1, own 2 cols
                u64 q0 = __shfl_xor_sync(0xffffffffu, up0, 1);
                u64 q1 = __shfl_xor_sync(0xffffffffu, up1, 1);
                float a0, a1, b0, b1;
                if ((tq & 1) == 0) {
                    unpack2(up0, a0, a1);
                    unpack2(q0, b0, b1);
                } else {
                    unpack2(q1, a0, a1);
                    unpack2(up1, b0, b1);
                }
                int colb = NB + nt * 8 + ((tq >> 1) << 2);  // 4-aligned col base
                if (colb < 128) {
                    red4(gp + colb, a0, a1, b0, b1);
                } else {
                    int m0 = colb - 128;      // even
                    float* p = gp + 128 + m0 * 3;
                    float v0 = a0 * y0, v1 = a0 * y1v, v2 = a0 * y2;
                    float v3 = a1 * y0, v4 = a1 * y1v, v5 = a1 * y2;
                    float v6 = b0 * y0, v7 = b0 * y1v, v8 = b0 * y2;
                    float v9 = b1 * y0, v10 = b1 * y1v, v11 = b1 * y2;
                    if ((m0 & 2) == 0) {      // 16B aligned
                        red4(p, v0, v1, v2, v3);
                        red4(p + 4, v4, v5, v6, v7);
                        red4(p + 8, v8, v9, v10, v11);
                    } else {                  // 8B aligned
                        red2(p, v0, v1);
                        red4(p + 2, v2, v3, v4, v5);
                        red4(p + 6, v6, v7, v8, v9);
                        red2(p + 10, v10, v11);
                    }
                }
            }
        }
        __syncthreads();
    }

    // ================= GRID BARRIER =================
    __threadfence();
    __syncthreads();
    if (tid == 0) {
        atomicAdd(&g_arrive, 1u);
        while (*(volatile unsigned int*)&g_arrive < (unsigned)gridDim.x)
            __nanosleep(128);
    }
    __syncthreads();
    __threadfence();

    // ================= NODE PHASE (proven scalar) =================
    float* smf = (float*)smem;
    float* Wm  = smf;
    float* b2f = smf + 24576;
    const int cg = lane;
    const int eg = wid;

    const float s_mix = 0.07216878364870323f;  // 1/sqrt(192)
    for (int i = tid; i < 192 * 128; i += NTHREADS) Wm[i] = Wmix0[i] * s_mix;
    __syncthreads();

    const int ntilesN = (NN + TN - 1) / TN;
    for (int tile = blockIdx.x; tile < ntilesN; tile += gridDim.x) {
        const int nbase = tile * TN;

        for (int idx = tid; idx < TN * 192; idx += NTHREADS) {
            int e = idx / 192, k = idx % 192;
            int n = nbase + e;
            float v = 0.f;
            if (n < NN) {
                if (k < 128) {
                    float a = g_A[(u64)n * FEAT + k];
                    v = a * a;
                } else {
                    int m = k - 128;
                    const float* p = &g_A[(u64)n * FEAT + 128 + m * 3];
                    float q0 = p[0], q1 = p[1], q2 = p[2];
                    v = (q0 * q0 + q1 * q1 + q2 * q2) * 0.5773502691896258f;
                }
            }
            b2f[((e >> 1) * 192 + k) * 2 + (e & 1)] = v;
        }
        __syncthreads();

        for (int idx = tid; idx < TN * 192; idx += NTHREADS) {
            int e = idx / 192, k = idx % 192;
            int n = nbase + e;
            if (n < NN) {
                u64 off = (u64)n * FEAT + 128 + k;
                out[off] = g_A[off];
                g_A[off] = 0.f;
            }
        }

        u64 acc[2][4];
#pragma unroll
        for (int p = 0; p < 2; p++)
#pragma unroll
            for (int c = 0; c < 4; c++) acc[p][c] = 0ull;
#pragma unroll 2
        for (int k = 0; k < 192; k++) {
            u64 a[2];
#pragma unroll
            for (int p = 0; p < 2; p++)
                a[p] = *(const u64*)&b2f[((eg * 2 + p) * 192 + k) * 2];
            float4 w4 = *(const float4*)&Wm[k * 128 + 4 * cg];
            u64 wd0 = pack2(w4.x, w4.x);
            u64 wd1 = pack2(w4.y, w4.y);
            u64 wd2 = pack2(w4.z, w4.z);
            u64 wd3 = pack2(w4.w, w4.w);
#pragma unroll
            for (int p = 0; p < 2; p++) {
                fma2(acc[p][0], a[p], wd0);
                fma2(acc[p][1], a[p], wd1);
                fma2(acc[p][2], a[p], wd2);
                fma2(acc[p][3], a[p], wd3);
            }
        }

#pragma unroll
        for (int p = 0; p < 2; p++) {
            int n0 = nbase + (eg * 2 + p) * 2;
            int n1 = n0 + 1;
            float a0, b0, a1, b1, a2, b2, a3, b3;
            unpack2(acc[p][0], a0, b0);
            unpack2(acc[p][1], a1, b1);
            unpack2(acc[p][2], a2, b2);
            unpack2(acc[p][3], a3, b3);
            if (n0 < NN) {
                u64 off = (u64)n0 * FEAT + 4 * cg;
                float4 A0 = *(const float4*)&g_A[off];
                *(float4*)&out[off] = make_float4(A0.x + a0, A0.y + a1, A0.z + a2, A0.w + a3);
                *(float4*)&g_A[off] = make_float4(0.f, 0.f, 0.f, 0.f);
            }
            if (n1 < NN) {
                u64 off = (u64)n1 * FEAT + 4 * cg;
                float4 A0 = *(const float4*)&g_A[off];
                *(float4*)&out[off] = make_float4(A0.x + b0, A0.y + b1, A0.z + b2, A0.w + b3);
                *(float4*)&g_A[off] = make_float4(0.f, 0.f, 0.f, 0.f);
            }
        }
        __syncthreads();
    }

    __syncthreads();
    if (tid == 0) {
        __threadfence();
        unsigned d = atomicAdd(&g_depart, 1u);
        if (d == (unsigned)gridDim.x - 1) {
            g_arrive = 0;
            g_depart = 0;
            __threadfence();
        }
    }
}

extern "C" void kernel_launch(void* const* d_in, const int* in_sizes, int n_in,
                              void* d_out, int out_size) {
    const float* node_attrs = (const float*)d_in[0];
    const int*   edge_index = (const int*)d_in[1];
    const float* edge_vec   = (const float*)d_in[2];
    const float* edge_len   = (const float*)d_in[3];
    const float* W1         = (const float*)d_in[4];
    const float* W2         = (const float*)d_in[5];
    const float* Wtp0       = (const float*)d_in[6];
    const float* Wtp1       = (const float*)d_in[7];
    const float* Wmix0      = (const float*)d_in[8];
    float* out = (float*)d_out;

    cudaFuncSetAttribute(ace_fused_kernel, cudaFuncAttributeMaxDynamicSharedMemorySize, SMEM_BYTES);

    ace_fused_kernel<<<NBLOCKS, NTHREADS, SMEM_BYTES>>>(
        node_attrs, edge_index, edge_vec, edge_len, W1, W2, Wtp0, Wtp1, Wmix0, out);
}

// round 14
// speedup vs baseline: 1.0059x; 1.0059x over previous
#include <cuda_runtime.h>
#include <cuda_bf16.h>
#include <math.h>

#define NN 50000
#define NE 400000
#define HID 128
#define FEAT 320
#define TEDGE 128
#define TN 64
#define NTHREADS 512
#define NBLOCKS 148

typedef unsigned long long u64;
typedef unsigned int u32;

// ---------------- smem byte offsets ----------------
#define OFF_WC_HI   0         // WC^T [192n][128k] bf16, 256B rows, swizzled
#define OFF_WC_LO   49152
#define OFF_W2_HI   98304     // W2^T [128c][64j] bf16, 128B rows
#define OFF_W2_LO   114688
#define OFF_NF_HI   131072    // nf [128e][128k] bf16, 256B rows
#define OFF_NF_LO   163840
#define OFF_H_HI    131072    // h [128e][64j] overlays NF_HI (dead after MMA C)
#define OFF_H_LO    147456
#define OFF_RAD     196608    // 128*9 floats
#define OFF_Y1      201216    // 128*4 floats
#define OFF_W1S     203264    // 512 floats
#define OFF_SND     205312
#define OFF_RCV     205824
#define SMEM_BYTES  206336

__device__ float g_A[(size_t)NN * FEAT];
__device__ unsigned int g_arrive;
__device__ unsigned int g_depart;

__device__ __forceinline__ u64 pack2(float a, float b) {
    u64 r; asm("mov.b64 %0, {%1,%2};" : "=l"(r) : "f"(a), "f"(b)); return r;
}
__device__ __forceinline__ void unpack2(u64 v, float& a, float& b) {
    asm("mov.b64 {%0,%1}, %2;" : "=f"(a), "=f"(b) : "l"(v));
}
__device__ __forceinline__ void fma2(u64& d, u64 a, u64 b) {
    asm("fma.rn.f32x2 %0, %1, %2, %0;" : "+l"(d) : "l"(a), "l"(b));
}
__device__ __forceinline__ void red4(float* p, float a, float b, float c, float d) {
    asm volatile("red.global.add.v4.f32 [%0], {%1,%2,%3,%4};"
                 :: "l"(p), "f"(a), "f"(b), "f"(c), "f"(d) : "memory");
}
__device__ __forceinline__ void red2(float* p, float a, float b) {
    asm volatile("red.global.add.v2.f32 [%0], {%1,%2};"
                 :: "l"(p), "f"(a), "f"(b) : "memory");
}
__device__ __forceinline__ u32 smem_u32_of(const void* p) {
    u32 a; asm("{ .reg .u64 t; cvta.to.shared.u64 t, %1; cvt.u32.u64 %0, t; }"
               : "=r"(a) : "l"(p));
    return a;
}
__device__ __forceinline__ u32 prmt7632(u32 a, u32 b) {
    u32 d; asm("prmt.b32 %0,%1,%2,0x7632;" : "=r"(d) : "r"(a), "r"(b)); return d;
}
__device__ __forceinline__ u32 cvt_bf2(float lo, float hi) {
    u32 d; asm("cvt.rn.bf16x2.f32 %0, %1, %2;" : "=r"(d) : "f"(hi), "f"(lo)); return d;
}
__device__ __forceinline__ void split2(float a, float b, u32& h, u32& l) {
    u32 au = __float_as_uint(a), bu = __float_as_uint(b);
    h = prmt7632(au, bu);
    l = cvt_bf2(a - __uint_as_float(au & 0xFFFF0000u),
                b - __uint_as_float(bu & 0xFFFF0000u));
}
__device__ __forceinline__ u32 swz(int row, int granule, int stride) {
    return (u32)(row * stride + (((granule ^ (row & 7)) << 4)));
}
__device__ __forceinline__ void lda(u32* f, u32 base, int R, int g0, int lane, int stride) {
    int row = R + (lane & 15);
    int g = g0 + (lane >> 4);
    u32 addr = base + swz(row, g, stride);
    asm volatile("ldmatrix.sync.aligned.m8n8.x4.shared.b16 {%0,%1,%2,%3}, [%4];"
                 : "=r"(f[0]), "=r"(f[1]), "=r"(f[2]), "=r"(f[3]) : "r"(addr));
}
__device__ __forceinline__ void ldb(u32* f, u32 base, int N0, int g0, int lane, int stride) {
    int n = N0 + (lane & 7) + ((lane >> 4) << 3);
    int g = g0 + ((lane >> 3) & 1);
    u32 addr = base + swz(n, g, stride);
    asm volatile("ldmatrix.sync.aligned.m8n8.x4.shared.b16 {%0,%1,%2,%3}, [%4];"
                 : "=r"(f[0]), "=r"(f[1]), "=r"(f[2]), "=r"(f[3]) : "r"(addr));
}
__device__ __forceinline__ void mma16816(float* d, const u32* a, u32 b0, u32 b1) {
    asm volatile("mma.sync.aligned.m16n8k16.row.col.f32.bf16.bf16.f32 "
                 "{%0,%1,%2,%3}, {%4,%5,%6,%7}, {%8,%9}, {%0,%1,%2,%3};"
                 : "+f"(d[0]), "+f"(d[1]), "+f"(d[2]), "+f"(d[3])
                 : "r"(a[0]), "r"(a[1]), "r"(a[2]), "r"(a[3]), "r"(b0), "r"(b1));
}

__global__ void __launch_bounds__(NTHREADS, 1)
ace_fused_kernel(const float* __restrict__ node_attrs,
                 const int* __restrict__ edge_index,
                 const float* __restrict__ edge_vec,
                 const float* __restrict__ edge_len,
                 const float* __restrict__ W1,
                 const float* __restrict__ W2,
                 const float* __restrict__ Wtp0,
                 const float* __restrict__ Wtp1,
                 const float* __restrict__ Wmix0,
                 float* __restrict__ out) {
    extern __shared__ char smem[];
    float* radS = (float*)(smem + OFF_RAD);
    float* y1S  = (float*)(smem + OFF_Y1);
    float* W1s  = (float*)(smem + OFF_W1S);
    int*   sndS = (int*)(smem + OFF_SND);
    int*   rcvS = (int*)(smem + OFF_RCV);

    const int tid = threadIdx.x;
    const int lane = tid & 31;
    const int wid = tid >> 5;
    const u32 sb = smem_u32_of(smem);

    // ---- stage weights: split bf16 hi/lo, swizzled ----
    for (int i = tid; i < 512; i += NTHREADS) W1s[i] = W1[i];
    for (int i = tid; i < 128 * 64; i += NTHREADS) {
        int c = i >> 6, j = i & 63;
        float v = W2[j * 128 + c];
        u32 vu = __float_as_uint(v);
        u32 off = swz(c, j >> 3, 128) + (j & 7) * 2;
        *(unsigned short*)(smem + OFF_W2_HI + off) = (unsigned short)(vu >> 16);
        *(__nv_bfloat16*)(smem + OFF_W2_LO + off) =
            __float2bfloat16(v - __uint_as_float(vu & 0xFFFF0000u));
    }
    for (int i = tid; i < 192 * 128; i += NTHREADS) {
        int n = i >> 7, k = i & 127;
        float v = (n < 128) ? Wtp0[k * 128 + n] : Wtp1[k * 64 + (n - 128)];
        u32 vu = __float_as_uint(v);
        u32 off = swz(n, k >> 3, 256) + (k & 7) * 2;
        *(unsigned short*)(smem + OFF_WC_HI + off) = (unsigned short)(vu >> 16);
        *(__nv_bfloat16*)(smem + OFF_WC_LO + off) =
            __float2bfloat16(v - __uint_as_float(vu & 0xFFFF0000u));
    }
    __syncthreads();

    const int wm = wid & 3;   // row group: 32 edges
    const int wn = wid >> 2;  // col group
    const int tq = lane & 3;  // quad thread
    const int gq = lane >> 2; // group row

    // ================= EDGE PHASE =================
    const int ntiles = NE / TEDGE;  // 3125
    for (int tile = blockIdx.x; tile < ntiles; tile += gridDim.x) {
        const int ebase = tile * TEDGE;

        // ---- Phase A: per-edge scalars ----
        if (tid < TEDGE) {
            int e = ebase + tid;
            float x = edge_len[e];
            bool valid = (x > 0.f) && (x < 5.0f);
            float pref = valid ? (0.22360679774997896f / x) : 0.f;  // sqrt(2/5)/x/sqrt(8)
#pragma unroll
            for (int r = 0; r < 8; r++)
                radS[tid * 9 + r] = pref * sinf((float)(r + 1) * 0.6283185307179586f * x);
            float vx = edge_vec[e * 3 + 0];
            float vy = edge_vec[e * 3 + 1];
            float vz = edge_vec[e * 3 + 2];
            float rn = rsqrtf(vx * vx + vy * vy + vz * vz) * 1.7320508075688772f;
            y1S[tid * 4 + 0] = vy * rn;
            y1S[tid * 4 + 1] = vz * rn;
            y1S[tid * 4 + 2] = vx * rn;
            sndS[tid] = edge_index[e];
            rcvS[tid] = edge_index[NE + e];
        }
        __syncthreads();

        // ---- Phase B: h = 0.018552463*silu(rad@W1), split bf16, swizzled ----
        {
            int e = tid >> 2;
            int j0 = (tid & 3) << 4;
            float hv[16];
#pragma unroll
            for (int i = 0; i < 16; i++) {
                float s = 0.f;
#pragma unroll
                for (int r = 0; r < 8; r++)
                    s += radS[e * 9 + r] * W1s[r * 64 + j0 + i];
                hv[i] = 0.018552463f * s / (1.f + __expf(-s));  // *SILU_2MOM*s_w2*s_tp
            }
            u32 hi[8], lo[8];
#pragma unroll
            for (int q = 0; q < 8; q++) split2(hv[2 * q], hv[2 * q + 1], hi[q], lo[q]);
            int x = j0 >> 3;
            u32 o0 = swz(e, x, 128), o1 = swz(e, x + 1, 128);
            *(uint4*)(smem + OFF_H_HI + o0) = make_uint4(hi[0], hi[1], hi[2], hi[3]);
            *(uint4*)(smem + OFF_H_HI + o1) = make_uint4(hi[4], hi[5], hi[6], hi[7]);
            *(uint4*)(smem + OFF_H_LO + o0) = make_uint4(lo[0], lo[1], lo[2], lo[3]);
            *(uint4*)(smem + OFF_H_LO + o1) = make_uint4(lo[4], lo[5], lo[6], lo[7]);
        }
        __syncthreads();

        // ---- MMA C: R_n[128e,128c] = h @ W2^T, split-bf16 3-pass ----
        float accc[2][4][4];
#pragma unroll
        for (int a = 0; a < 2; a++)
#pragma unroll
            for (int b = 0; b < 4; b++)
#pragma unroll
                for (int c = 0; c < 4; c++) accc[a][b][c] = 0.f;
#pragma unroll
        for (int k = 0; k < 4; k++) {
            int g0 = 2 * k;
            u32 ah0[4], ah1[4], al0[4], al1[4];
            lda(ah0, sb + OFF_H_HI, wm * 32,      g0, lane, 128);
            lda(ah1, sb + OFF_H_HI, wm * 32 + 16, g0, lane, 128);
            lda(al0, sb + OFF_H_LO, wm * 32,      g0, lane, 128);
            lda(al1, sb + OFF_H_LO, wm * 32 + 16, g0, lane, 128);
#pragma unroll
            for (int np = 0; np < 2; np++) {
                u32 bh[4], bl[4];
                ldb(bh, sb + OFF_W2_HI, wn * 32 + np * 16, g0, lane, 128);
                ldb(bl, sb + OFF_W2_LO, wn * 32 + np * 16, g0, lane, 128);
                mma16816(accc[0][2 * np],     ah0, bh[0], bh[1]);
                mma16816(accc[0][2 * np + 1], ah0, bh[2], bh[3]);
                mma16816(accc[1][2 * np],     ah1, bh[0], bh[1]);
                mma16816(accc[1][2 * np + 1], ah1, bh[2], bh[3]);
                mma16816(accc[0][2 * np],     al0, bh[0], bh[1]);
                mma16816(accc[0][2 * np + 1], al0, bh[2], bh[3]);
                mma16816(accc[1][2 * np],     al1, bh[0], bh[1]);
                mma16816(accc[1][2 * np + 1], al1, bh[2], bh[3]);
                mma16816(accc[0][2 * np],     ah0, bl[0], bl[1]);
                mma16816(accc[0][2 * np + 1], ah0, bl[2], bl[3]);
                mma16816(accc[1][2 * np],     ah1, bl[0], bl[1]);
                mma16816(accc[1][2 * np + 1], ah1, bl[2], bl[3]);
            }
        }

        // ---- readout C: gather + multiply + split into regs BEFORE barrier ----
        // (accc dies into nfh/nfl -> no net register growth; loads batched by ptxas)
        u32 nfh[2][2][4], nfl[2][2][4];
#pragma unroll
        for (int mt = 0; mt < 2; mt++) {
            int r0 = wm * 32 + mt * 16 + gq;
            int s0 = sndS[r0], s1 = sndS[r0 + 8];
            const float* b0p = node_attrs + (u64)s0 * HID + wn * 32 + 2 * tq;
            const float* b1p = node_attrs + (u64)s1 * HID + wn * 32 + 2 * tq;
#pragma unroll
            for (int nt = 0; nt < 4; nt++) {
                float2 a0 = *(const float2*)(b0p + nt * 8);
                float2 a1 = *(const float2*)(b1p + nt * 8);
                split2(accc[mt][nt][0] * a0.x, accc[mt][nt][1] * a0.y,
                       nfh[mt][0][nt], nfl[mt][0][nt]);
                split2(accc[mt][nt][2] * a1.x, accc[mt][nt][3] * a1.y,
                       nfh[mt][1][nt], nfl[mt][1][nt]);
            }
        }
        __syncthreads();   // all warps done reading h before nf overlays it

        // ---- store nf to smem (swizzled) ----
#pragma unroll
        for (int mt = 0; mt < 2; mt++) {
            int r0 = wm * 32 + mt * 16 + gq;
            int r1 = r0 + 8;
#pragma unroll
            for (int nt = 0; nt < 4; nt++) {
                int col = wn * 32 + nt * 8 + 2 * tq;
                u32 o0 = swz(r0, col >> 3, 256) + (col & 7) * 2;
                u32 o1 = swz(r1, col >> 3, 256) + (col & 7) * 2;
                *(u32*)(smem + OFF_NF_HI + o0) = nfh[mt][0][nt];
                *(u32*)(smem + OFF_NF_LO + o0) = nfl[mt][0][nt];
                *(u32*)(smem + OFF_NF_HI + o1) = nfh[mt][1][nt];
                *(u32*)(smem + OFF_NF_LO + o1) = nfl[mt][1][nt];
            }
        }
        __syncthreads();

        // ---- MMA D: [f0|t1][128e,192n] = nf @ WC^T, split-bf16 3-pass ----
        float accd[2][6][4];
#pragma unroll
        for (int a = 0; a < 2; a++)
#pragma unroll
            for (int b = 0; b < 6; b++)
#pragma unroll
                for (int c = 0; c < 4; c++) accd[a][b][c] = 0.f;
        const int NB = wn * 48;
#pragma unroll
        for (int k = 0; k < 8; k++) {
            int g0 = 2 * k;
            u32 ah0[4], ah1[4], al0[4], al1[4];
            lda(ah0, sb + OFF_NF_HI, wm * 32,      g0, lane, 256);
            lda(ah1, sb + OFF_NF_HI, wm * 32 + 16, g0, lane, 256);
            lda(al0, sb + OFF_NF_LO, wm * 32,      g0, lane, 256);
            lda(al1, sb + OFF_NF_LO, wm * 32 + 16, g0, lane, 256);
#pragma unroll
            for (int np = 0; np < 3; np++) {
                u32 bh[4], bl[4];
                ldb(bh, sb + OFF_WC_HI, NB + np * 16, g0, lane, 256);
                ldb(bl, sb + OFF_WC_LO, NB + np * 16, g0, lane, 256);
                mma16816(accd[0][2 * np],     ah0, bh[0], bh[1]);
                mma16816(accd[0][2 * np + 1], ah0, bh[2], bh[3]);
                mma16816(accd[1][2 * np],     ah1, bh[0], bh[1]);
                mma16816(accd[1][2 * np + 1], ah1, bh[2], bh[3]);
                mma16816(accd[0][2 * np],     al0, bh[0], bh[1]);
                mma16816(accd[0][2 * np + 1], al0, bh[2], bh[3]);
                mma16816(accd[1][2 * np],     al1, bh[0], bh[1]);
                mma16816(accd[1][2 * np + 1], al1, bh[2], bh[3]);
                mma16816(accd[0][2 * np],     ah0, bl[0], bl[1]);
                mma16816(accd[0][2 * np + 1], ah0, bl[2], bl[3]);
                mma16816(accd[1][2 * np],     ah1, bl[0], bl[1]);
                mma16816(accd[1][2 * np + 1], ah1, bl[2], bl[3]);
            }
        }

        // ---- scatter: quad-pair merge via shfl -> red4 (halves L2 requests) ----
#pragma unroll
        for (int mt = 0; mt < 2; mt++) {
            int r0 = wm * 32 + mt * 16 + gq;
            int r1 = r0 + 8;
            int myrow = (tq & 1) ? r1 : r0;
            float* gp = g_A + (u64)rcvS[myrow] * FEAT;
            float y0 = y1S[myrow * 4 + 0];
            float y1v = y1S[myrow * 4 + 1];
            float y2 = y1S[myrow * 4 + 2];
#pragma unroll
            for (int nt = 0; nt < 6; nt++) {
                u64 up0 = pack2(accd[mt][nt][0], accd[mt][nt][1]);  // row r0, own 2 cols
                u64 up1 = pack2(accd[mt][nt][2], accd[mt][nt][3]);  // row r1, own 2 cols
                u64 q0 = __shfl_xor_sync(0xffffffffu, up0, 1);
                u64 q1 = __shfl_xor_sync(0xffffffffu, up1, 1);
                float a0, a1, b0, b1;
                if ((tq & 1) == 0) {
                    unpack2(up0, a0, a1);
                    unpack2(q0, b0, b1);
                } else {
                    unpack2(q1, a0, a1);
                    unpack2(up1, b0, b1);
                }
                int colb = NB + nt * 8 + ((tq >> 1) << 2);  // 4-aligned col base
                if (colb < 128) {
                    red4(gp + colb, a0, a1, b0, b1);
                } else {
                    int m0 = colb - 128;      // even
                    float* p = gp + 128 + m0 * 3;
                    float v0 = a0 * y0, v1 = a0 * y1v, v2 = a0 * y2;
                    float v3 = a1 * y0, v4 = a1 * y1v, v5 = a1 * y2;
                    float v6 = b0 * y0, v7 = b0 * y1v, v8 = b0 * y2;
                    float v9 = b1 * y0, v10 = b1 * y1v, v11 = b1 * y2;
                    if ((m0 & 2) == 0) {      // 16B aligned
                        red4(p, v0, v1, v2, v3);
                        red4(p + 4, v4, v5, v6, v7);
                        red4(p + 8, v8, v9, v10, v11);
                    } else {                  // 8B aligned
                        red2(p, v0, v1);
                        red4(p + 2, v2, v3, v4, v5);
                        red4(p + 6, v6, v7, v8, v9);
                        red2(p + 10, v10, v11);
                    }
                }
            }
        }
        __syncthreads();
    }

    // ================= GRID BARRIER =================
    __threadfence();
    __syncthreads();
    if (tid == 0) {
        atomicAdd(&g_arrive, 1u);
        while (*(volatile unsigned int*)&g_arrive < (unsigned)gridDim.x)
            __nanosleep(128);
    }
    __syncthreads();
    __threadfence();

    // ================= NODE PHASE (proven scalar) =================
    float* smf = (float*)smem;
    float* Wm  = smf;
    float* b2f = smf + 24576;
    const int cg = lane;
    const int eg = wid;

    const float s_mix = 0.07216878364870323f;  // 1/sqrt(192)
    for (int i = tid; i < 192 * 128; i += NTHREADS) Wm[i] = Wmix0[i] * s_mix;
    __syncthreads();

    const int ntilesN = (NN + TN - 1) / TN;
    for (int tile = blockIdx.x; tile < ntilesN; tile += gridDim.x) {
        const int nbase = tile * TN;

        for (int idx = tid; idx < TN * 192; idx += NTHREADS) {
            int e = idx / 192, k = idx % 192;
            int n = nbase + e;
            float v = 0.f;
            if (n < NN) {
                if (k < 128) {
                    float a = g_A[(u64)n * FEAT + k];
                    v = a * a;
                } else {
                    int m = k - 128;
                    const float* p = &g_A[(u64)n * FEAT + 128 + m * 3];
                    float q0 = p[0], q1 = p[1], q2 = p[2];
                    v = (q0 * q0 + q1 * q1 + q2 * q2) * 0.5773502691896258f;
                }
            }
            b2f[((e >> 1) * 192 + k) * 2 + (e & 1)] = v;
        }
        __syncthreads();

        for (int idx = tid; idx < TN * 192; idx += NTHREADS) {
            int e = idx / 192, k = idx % 192;
            int n = nbase + e;
            if (n < NN) {
                u64 off = (u64)n * FEAT + 128 + k;
                out[off] = g_A[off];
                g_A[off] = 0.f;
            }
        }

        u64 acc[2][4];
#pragma unroll
        for (int p = 0; p < 2; p++)
#pragma unroll
            for (int c = 0; c < 4; c++) acc[p][c] = 0ull;
#pragma unroll 2
        for (int k = 0; k < 192; k++) {
            u64 a[2];
#pragma unroll
            for (int p = 0; p < 2; p++)
                a[p] = *(const u64*)&b2f[((eg * 2 + p) * 192 + k) * 2];
            float4 w4 = *(const float4*)&Wm[k * 128 + 4 * cg];
            u64 wd0 = pack2(w4.x, w4.x);
            u64 wd1 = pack2(w4.y, w4.y);
            u64 wd2 = pack2(w4.z, w4.z);
            u64 wd3 = pack2(w4.w, w4.w);
#pragma unroll
            for (int p = 0; p < 2; p++) {
                fma2(acc[p][0], a[p], wd0);
                fma2(acc[p][1], a[p], wd1);
                fma2(acc[p][2], a[p], wd2);
                fma2(acc[p][3], a[p], wd3);
            }
        }

#pragma unroll
        for (int p = 0; p < 2; p++) {
            int n0 = nbase + (eg * 2 + p) * 2;
            int n1 = n0 + 1;
            float a0, b0, a1, b1, a2, b2, a3, b3;
            unpack2(acc[p][0], a0, b0);
            unpack2(acc[p][1], a1, b1);
            unpack2(acc[p][2], a2, b2);
            unpack2(acc[p][3], a3, b3);
            if (n0 < NN) {
                u64 off = (u64)n0 * FEAT + 4 * cg;
                float4 A0 = *(const float4*)&g_A[off];
                *(float4*)&out[off] = make_float4(A0.x + a0, A0.y + a1, A0.z + a2, A0.w + a3);
                *(float4*)&g_A[off] = make_float4(0.f, 0.f, 0.f, 0.f);
            }
            if (n1 < NN) {
                u64 off = (u64)n1 * FEAT + 4 * cg;
                float4 A0 = *(const float4*)&g_A[off];
                *(float4*)&out[off] = make_float4(A0.x + b0, A0.y + b1, A0.z + b2, A0.w + b3);
                *(float4*)&g_A[off] = make_float4(0.f, 0.f, 0.f, 0.f);
            }
        }
        __syncthreads();
    }

    __syncthreads();
    if (tid == 0) {
        __threadfence();
        unsigned d = atomicAdd(&g_depart, 1u);
        if (d == (unsigned)gridDim.x - 1) {
            g_arrive = 0;
            g_depart = 0;
            __threadfence();
        }
    }
}

extern "C" void kernel_launch(void* const* d_in, const int* in_sizes, int n_in,
                              void* d_out, int out_size) {
    const float* node_attrs = (const float*)d_in[0];
    const int*   edge_index = (const int*)d_in[1];
    const float* edge_vec   = (const float*)d_in[2];
    const float* edge_len   = (const float*)d_in[3];
    const float* W1         = (const float*)d_in[4];
    const float* W2         = (const float*)d_in[5];
    const float* Wtp0       = (const float*)d_in[6];
    const float* Wtp1       = (const float*)d_in[7];
    const float* Wmix0      = (const float*)d_in[8];
    float* out = (float*)d_out;

    cudaFuncSetAttribute(ace_fused_kernel, cudaFuncAttributeMaxDynamicSharedMemorySize, SMEM_BYTES);

    ace_fused_kernel<<<NBLOCKS, NTHREADS, SMEM_BYTES>>>(
        node_attrs, edge_index, edge_vec, edge_len, W1, W2, Wtp0, Wtp1, Wmix0, out);
}

// round 15
// speedup vs baseline: 1.0849x; 1.0785x over previous
#include <cuda_runtime.h>
#include <cuda_bf16.h>
#include <math.h>

#define NN 50000
#define NE 400000
#define HID 128
#define FEAT 320
#define TEDGE 128
#define TN 64
#define NTHREADS 512
#define NBLOCKS 148

typedef unsigned long long u64;
typedef unsigned int u32;

// ---------------- smem byte offsets (edge phase) ----------------
#define OFF_WC_HI   0         // WC^T [192n][128k] bf16, 256B rows, swizzled
#define OFF_WC_LO   49152
#define OFF_W2_HI   98304     // W2^T [128c][64j] bf16, 128B rows
#define OFF_W2_LO   114688
#define OFF_NF_HI   131072    // nf [128e][128k] bf16, 256B rows
#define OFF_NF_LO   163840
#define OFF_H_HI    131072    // h [128e][64j] overlays NF_HI (dead after MMA C)
#define OFF_H_LO    147456
#define OFF_RAD     196608    // 128*9 floats
#define OFF_Y1      201216    // 128*4 floats
#define OFF_W1S     203264    // 512 floats
#define OFF_SND     205312
#define OFF_RCV     205824
#define SMEM_BYTES  206336
// node phase overlays: WM_HI @0 (48KB), WM_LO @49152 (48KB)  [dead WC region]
//                      B0_HI @131072 (24KB), B0_LO @155648 (24KB) [dead NF region]
#define OFF_WM_HI   0
#define OFF_WM_LO   49152
#define OFF_B0_HI   131072
#define OFF_B0_LO   155648

__device__ float g_A[(size_t)NN * FEAT];
__device__ unsigned int g_arrive;
__device__ unsigned int g_depart;

__device__ __forceinline__ u64 pack2(float a, float b) {
    u64 r; asm("mov.b64 %0, {%1,%2};" : "=l"(r) : "f"(a), "f"(b)); return r;
}
__device__ __forceinline__ void unpack2(u64 v, float& a, float& b) {
    asm("mov.b64 {%0,%1}, %2;" : "=f"(a), "=f"(b) : "l"(v));
}
__device__ __forceinline__ void red4(float* p, float a, float b, float c, float d) {
    asm volatile("red.global.add.v4.f32 [%0], {%1,%2,%3,%4};"
                 :: "l"(p), "f"(a), "f"(b), "f"(c), "f"(d) : "memory");
}
__device__ __forceinline__ void red2(float* p, float a, float b) {
    asm volatile("red.global.add.v2.f32 [%0], {%1,%2};"
                 :: "l"(p), "f"(a), "f"(b) : "memory");
}
__device__ __forceinline__ u32 smem_u32_of(const void* p) {
    u32 a; asm("{ .reg .u64 t; cvta.to.shared.u64 t, %1; cvt.u32.u64 %0, t; }"
               : "=r"(a) : "l"(p));
    return a;
}
__device__ __forceinline__ u32 prmt7632(u32 a, u32 b) {
    u32 d; asm("prmt.b32 %0,%1,%2,0x7632;" : "=r"(d) : "r"(a), "r"(b)); return d;
}
__device__ __forceinline__ u32 cvt_bf2(float lo, float hi) {
    u32 d; asm("cvt.rn.bf16x2.f32 %0, %1, %2;" : "=r"(d) : "f"(hi), "f"(lo)); return d;
}
__device__ __forceinline__ void split2(float a, float b, u32& h, u32& l) {
    u32 au = __float_as_uint(a), bu = __float_as_uint(b);
    h = prmt7632(au, bu);
    l = cvt_bf2(a - __uint_as_float(au & 0xFFFF0000u),
                b - __uint_as_float(bu & 0xFFFF0000u));
}
__device__ __forceinline__ u32 swz(int row, int granule, int stride) {
    return (u32)(row * stride + (((granule ^ (row & 7)) << 4)));
}
__device__ __forceinline__ void lda(u32* f, u32 base, int R, int g0, int lane, int stride) {
    int row = R + (lane & 15);
    int g = g0 + (lane >> 4);
    u32 addr = base + swz(row, g, stride);
    asm volatile("ldmatrix.sync.aligned.m8n8.x4.shared.b16 {%0,%1,%2,%3}, [%4];"
                 : "=r"(f[0]), "=r"(f[1]), "=r"(f[2]), "=r"(f[3]) : "r"(addr));
}
__device__ __forceinline__ void ldb(u32* f, u32 base, int N0, int g0, int lane, int stride) {
    int n = N0 + (lane & 7) + ((lane >> 4) << 3);
    int g = g0 + ((lane >> 3) & 1);
    u32 addr = base + swz(n, g, stride);
    asm volatile("ldmatrix.sync.aligned.m8n8.x4.shared.b16 {%0,%1,%2,%3}, [%4];"
                 : "=r"(f[0]), "=r"(f[1]), "=r"(f[2]), "=r"(f[3]) : "r"(addr));
}
__device__ __forceinline__ void mma16816(float* d, const u32* a, u32 b0, u32 b1) {
    asm volatile("mma.sync.aligned.m16n8k16.row.col.f32.bf16.bf16.f32 "
                 "{%0,%1,%2,%3}, {%4,%5,%6,%7}, {%8,%9}, {%0,%1,%2,%3};"
                 : "+f"(d[0]), "+f"(d[1]), "+f"(d[2]), "+f"(d[3])
                 : "r"(a[0]), "r"(a[1]), "r"(a[2]), "r"(a[3]), "r"(b0), "r"(b1));
}

__global__ void __launch_bounds__(NTHREADS, 1)
ace_fused_kernel(const float* __restrict__ node_attrs,
                 const int* __restrict__ edge_index,
                 const float* __restrict__ edge_vec,
                 const float* __restrict__ edge_len,
                 const float* __restrict__ W1,
                 const float* __restrict__ W2,
                 const float* __restrict__ Wtp0,
                 const float* __restrict__ Wtp1,
                 const float* __restrict__ Wmix0,
                 float* __restrict__ out) {
    extern __shared__ char smem[];
    float* radS = (float*)(smem + OFF_RAD);
    float* y1S  = (float*)(smem + OFF_Y1);
    float* W1s  = (float*)(smem + OFF_W1S);
    int*   sndS = (int*)(smem + OFF_SND);
    int*   rcvS = (int*)(smem + OFF_RCV);

    const int tid = threadIdx.x;
    const int lane = tid & 31;
    const int wid = tid >> 5;
    const u32 sb = smem_u32_of(smem);

    // ---- stage weights: split bf16 hi/lo, swizzled ----
    for (int i = tid; i < 512; i += NTHREADS) W1s[i] = W1[i];
    for (int i = tid; i < 128 * 64; i += NTHREADS) {
        int c = i >> 6, j = i & 63;
        float v = W2[j * 128 + c];
        u32 vu = __float_as_uint(v);
        u32 off = swz(c, j >> 3, 128) + (j & 7) * 2;
        *(unsigned short*)(smem + OFF_W2_HI + off) = (unsigned short)(vu >> 16);
        *(__nv_bfloat16*)(smem + OFF_W2_LO + off) =
            __float2bfloat16(v - __uint_as_float(vu & 0xFFFF0000u));
    }
    for (int i = tid; i < 192 * 128; i += NTHREADS) {
        int n = i >> 7, k = i & 127;
        float v = (n < 128) ? Wtp0[k * 128 + n] : Wtp1[k * 64 + (n - 128)];
        u32 vu = __float_as_uint(v);
        u32 off = swz(n, k >> 3, 256) + (k & 7) * 2;
        *(unsigned short*)(smem + OFF_WC_HI + off) = (unsigned short)(vu >> 16);
        *(__nv_bfloat16*)(smem + OFF_WC_LO + off) =
            __float2bfloat16(v - __uint_as_float(vu & 0xFFFF0000u));
    }
    __syncthreads();

    const int wm = wid & 3;   // row group
    const int wn = wid >> 2;  // col group
    const int tq = lane & 3;  // quad thread
    const int gq = lane >> 2; // group row

    // ================= EDGE PHASE (exact R12) =================
    const int ntiles = NE / TEDGE;  // 3125
    for (int tile = blockIdx.x; tile < ntiles; tile += gridDim.x) {
        const int ebase = tile * TEDGE;

        if (tid < TEDGE) {
            int e = ebase + tid;
            float x = edge_len[e];
            bool valid = (x > 0.f) && (x < 5.0f);
            float pref = valid ? (0.22360679774997896f / x) : 0.f;
#pragma unroll
            for (int r = 0; r < 8; r++)
                radS[tid * 9 + r] = pref * sinf((float)(r + 1) * 0.6283185307179586f * x);
            float vx = edge_vec[e * 3 + 0];
            float vy = edge_vec[e * 3 + 1];
            float vz = edge_vec[e * 3 + 2];
            float rn = rsqrtf(vx * vx + vy * vy + vz * vz) * 1.7320508075688772f;
            y1S[tid * 4 + 0] = vy * rn;
            y1S[tid * 4 + 1] = vz * rn;
            y1S[tid * 4 + 2] = vx * rn;
            sndS[tid] = edge_index[e];
            rcvS[tid] = edge_index[NE + e];
        }
        __syncthreads();

        {
            int e = tid >> 2;
            int j0 = (tid & 3) << 4;
            float hv[16];
#pragma unroll
            for (int i = 0; i < 16; i++) {
                float s = 0.f;
#pragma unroll
                for (int r = 0; r < 8; r++)
                    s += radS[e * 9 + r] * W1s[r * 64 + j0 + i];
                hv[i] = 0.018552463f * s / (1.f + __expf(-s));
            }
            u32 hi[8], lo[8];
#pragma unroll
            for (int q = 0; q < 8; q++) split2(hv[2 * q], hv[2 * q + 1], hi[q], lo[q]);
            int x = j0 >> 3;
            u32 o0 = swz(e, x, 128), o1 = swz(e, x + 1, 128);
            *(uint4*)(smem + OFF_H_HI + o0) = make_uint4(hi[0], hi[1], hi[2], hi[3]);
            *(uint4*)(smem + OFF_H_HI + o1) = make_uint4(hi[4], hi[5], hi[6], hi[7]);
            *(uint4*)(smem + OFF_H_LO + o0) = make_uint4(lo[0], lo[1], lo[2], lo[3]);
            *(uint4*)(smem + OFF_H_LO + o1) = make_uint4(lo[4], lo[5], lo[6], lo[7]);
        }
        __syncthreads();

        float accc[2][4][4];
#pragma unroll
        for (int a = 0; a < 2; a++)
#pragma unroll
            for (int b = 0; b < 4; b++)
#pragma unroll
                for (int c = 0; c < 4; c++) accc[a][b][c] = 0.f;
#pragma unroll
        for (int k = 0; k < 4; k++) {
            int g0 = 2 * k;
            u32 ah0[4], ah1[4], al0[4], al1[4];
            lda(ah0, sb + OFF_H_HI, wm * 32,      g0, lane, 128);
            lda(ah1, sb + OFF_H_HI, wm * 32 + 16, g0, lane, 128);
            lda(al0, sb + OFF_H_LO, wm * 32,      g0, lane, 128);
            lda(al1, sb + OFF_H_LO, wm * 32 + 16, g0, lane, 128);
#pragma unroll
            for (int np = 0; np < 2; np++) {
                u32 bh[4], bl[4];
                ldb(bh, sb + OFF_W2_HI, wn * 32 + np * 16, g0, lane, 128);
                ldb(bl, sb + OFF_W2_LO, wn * 32 + np * 16, g0, lane, 128);
                mma16816(accc[0][2 * np],     ah0, bh[0], bh[1]);
                mma16816(accc[0][2 * np + 1], ah0, bh[2], bh[3]);
                mma16816(accc[1][2 * np],     ah1, bh[0], bh[1]);
                mma16816(accc[1][2 * np + 1], ah1, bh[2], bh[3]);
                mma16816(accc[0][2 * np],     al0, bh[0], bh[1]);
                mma16816(accc[0][2 * np + 1], al0, bh[2], bh[3]);
                mma16816(accc[1][2 * np],     al1, bh[0], bh[1]);
                mma16816(accc[1][2 * np + 1], al1, bh[2], bh[3]);
                mma16816(accc[0][2 * np],     ah0, bl[0], bl[1]);
                mma16816(accc[0][2 * np + 1], ah0, bl[2], bl[3]);
                mma16816(accc[1][2 * np],     ah1, bl[0], bl[1]);
                mma16816(accc[1][2 * np + 1], ah1, bl[2], bl[3]);
            }
        }
        __syncthreads();

        // ---- readout C (R12 form): gather + multiply + split + store ----
#pragma unroll
        for (int mt = 0; mt < 2; mt++) {
            int r0 = wm * 32 + mt * 16 + gq;
            int r1 = r0 + 8;
            int s0 = sndS[r0], s1 = sndS[r1];
#pragma unroll
            for (int nt = 0; nt < 4; nt++) {
                int col = wn * 32 + nt * 8 + 2 * tq;
                float2 a0 = *(const float2*)&node_attrs[(u64)s0 * HID + col];
                float2 a1 = *(const float2*)&node_attrs[(u64)s1 * HID + col];
                float v00 = accc[mt][nt][0] * a0.x, v01 = accc[mt][nt][1] * a0.y;
                float v10 = accc[mt][nt][2] * a1.x, v11 = accc[mt][nt][3] * a1.y;
                u32 h0, l0, h1, l1;
                split2(v00, v01, h0, l0);
                split2(v10, v11, h1, l1);
                u32 o0 = swz(r0, col >> 3, 256) + (col & 7) * 2;
                u32 o1 = swz(r1, col >> 3, 256) + (col & 7) * 2;
                *(u32*)(smem + OFF_NF_HI + o0) = h0;
                *(u32*)(smem + OFF_NF_LO + o0) = l0;
                *(u32*)(smem + OFF_NF_HI + o1) = h1;
                *(u32*)(smem + OFF_NF_LO + o1) = l1;
            }
        }
        __syncthreads();

        float accd[2][6][4];
#pragma unroll
        for (int a = 0; a < 2; a++)
#pragma unroll
            for (int b = 0; b < 6; b++)
#pragma unroll
                for (int c = 0; c < 4; c++) accd[a][b][c] = 0.f;
        const int NB = wn * 48;
#pragma unroll
        for (int k = 0; k < 8; k++) {
            int g0 = 2 * k;
            u32 ah0[4], ah1[4], al0[4], al1[4];
            lda(ah0, sb + OFF_NF_HI, wm * 32,      g0, lane, 256);
            lda(ah1, sb + OFF_NF_HI, wm * 32 + 16, g0, lane, 256);
            lda(al0, sb + OFF_NF_LO, wm * 32,      g0, lane, 256);
            lda(al1, sb + OFF_NF_LO, wm * 32 + 16, g0, lane, 256);
#pragma unroll
            for (int np = 0; np < 3; np++) {
                u32 bh[4], bl[4];
                ldb(bh, sb + OFF_WC_HI, NB + np * 16, g0, lane, 256);
                ldb(bl, sb + OFF_WC_LO, NB + np * 16, g0, lane, 256);
                mma16816(accd[0][2 * np],     ah0, bh[0], bh[1]);
                mma16816(accd[0][2 * np + 1], ah0, bh[2], bh[3]);
                mma16816(accd[1][2 * np],     ah1, bh[0], bh[1]);
                mma16816(accd[1][2 * np + 1], ah1, bh[2], bh[3]);
                mma16816(accd[0][2 * np],     al0, bh[0], bh[1]);
                mma16816(accd[0][2 * np + 1], al0, bh[2], bh[3]);
                mma16816(accd[1][2 * np],     al1, bh[0], bh[1]);
                mma16816(accd[1][2 * np + 1], al1, bh[2], bh[3]);
                mma16816(accd[0][2 * np],     ah0, bl[0], bl[1]);
                mma16816(accd[0][2 * np + 1], ah0, bl[2], bl[3]);
                mma16816(accd[1][2 * np],     ah1, bl[0], bl[1]);
                mma16816(accd[1][2 * np + 1], ah1, bl[2], bl[3]);
            }
        }

        // ---- scatter: quad-pair merge via shfl -> red4 ----
#pragma unroll
        for (int mt = 0; mt < 2; mt++) {
            int r0 = wm * 32 + mt * 16 + gq;
            int r1 = r0 + 8;
            int myrow = (tq & 1) ? r1 : r0;
            float* gp = g_A + (u64)rcvS[myrow] * FEAT;
            float y0 = y1S[myrow * 4 + 0];
            float y1v = y1S[myrow * 4 + 1];
            float y2 = y1S[myrow * 4 + 2];
#pragma unroll
            for (int nt = 0; nt < 6; nt++) {
                u64 up0 = pack2(accd[mt][nt][0], accd[mt][nt][1]);
                u64 up1 = pack2(accd[mt][nt][2], accd[mt][nt][3]);
                u64 q0 = __shfl_xor_sync(0xffffffffu, up0, 1);
                u64 q1 = __shfl_xor_sync(0xffffffffu, up1, 1);
                float a0, a1, b0, b1;
                if ((tq & 1) == 0) {
                    unpack2(up0, a0, a1);
                    unpack2(q0, b0, b1);
                } else {
                    unpack2(q1, a0, a1);
                    unpack2(up1, b0, b1);
                }
                int colb = NB + nt * 8 + ((tq >> 1) << 2);
                if (colb < 128) {
                    red4(gp + colb, a0, a1, b0, b1);
                } else {
                    int m0 = colb - 128;
                    float* p = gp + 128 + m0 * 3;
                    float v0 = a0 * y0, v1 = a0 * y1v, v2 = a0 * y2;
                    float v3 = a1 * y0, v4 = a1 * y1v, v5 = a1 * y2;
                    float v6 = b0 * y0, v7 = b0 * y1v, v8 = b0 * y2;
                    float v9 = b1 * y0, v10 = b1 * y1v, v11 = b1 * y2;
                    if ((m0 & 2) == 0) {
                        red4(p, v0, v1, v2, v3);
                        red4(p + 4, v4, v5, v6, v7);
                        red4(p + 8, v8, v9, v10, v11);
                    } else {
                        red2(p, v0, v1);
                        red4(p + 2, v2, v3, v4, v5);
                        red4(p + 6, v6, v7, v8, v9);
                        red2(p + 10, v10, v11);
                    }
                }
            }
        }
        __syncthreads();
    }

    // ================= GRID BARRIER =================
    __threadfence();
    __syncthreads();
    if (tid == 0) {
        atomicAdd(&g_arrive, 1u);
        while (*(volatile unsigned int*)&g_arrive < (unsigned)gridDim.x)
            __nanosleep(128);
    }
    __syncthreads();
    __threadfence();

    // ================= NODE PHASE (split-bf16 HMMA) =================
    // stage Wmix0' split: [128c][192k] bf16, 384B rows, swizzled
    const float s_mix = 0.07216878364870323f;  // 1/sqrt(192)
    for (int i = tid; i < 128 * 192; i += NTHREADS) {
        int c = i / 192, k = i % 192;
        float v = Wmix0[k * 128 + c] * s_mix;
        u32 vu = __float_as_uint(v);
        u32 off = swz(c, k >> 3, 384) + (k & 7) * 2;
        *(unsigned short*)(smem + OFF_WM_HI + off) = (unsigned short)(vu >> 16);
        *(__nv_bfloat16*)(smem + OFF_WM_LO + off) =
            __float2bfloat16(v - __uint_as_float(vu & 0xFFFF0000u));
    }
    __syncthreads();

    const int ntilesN = (NN + TN - 1) / TN;  // 782
    for (int tile = blockIdx.x; tile < ntilesN; tile += gridDim.x) {
        const int nbase = tile * TN;

        // ---- build B0 split tiles [64n][192k] bf16 hi/lo ----
        {
            int n = tid >> 3;            // 0..63
            int k0 = (tid & 7) * 24;     // 24 consecutive k per thread
            int ng = nbase + n;
            float v[24];
            if (ng < NN) {
                const float* gp = g_A + (u64)ng * FEAT;
#pragma unroll
                for (int i = 0; i < 24; i++) {
                    int k = k0 + i;
                    if (k < 128) {
                        float a = gp[k];
                        v[i] = a * a;
                    } else {
                        int m = k - 128;
                        float q0 = gp[128 + m * 3], q1 = gp[128 + m * 3 + 1], q2 = gp[128 + m * 3 + 2];
                        v[i] = (q0 * q0 + q1 * q1 + q2 * q2) * 0.5773502691896258f;
                    }
                }
            } else {
#pragma unroll
                for (int i = 0; i < 24; i++) v[i] = 0.f;
            }
            u32 hi[12], lo[12];
#pragma unroll
            for (int q = 0; q < 12; q++) split2(v[2 * q], v[2 * q + 1], hi[q], lo[q]);
            int gbase = 3 * (tid & 7);
#pragma unroll
            for (int j = 0; j < 3; j++) {
                u32 off = swz(n, gbase + j, 384);
                *(uint4*)(smem + OFF_B0_HI + off) =
                    make_uint4(hi[4 * j], hi[4 * j + 1], hi[4 * j + 2], hi[4 * j + 3]);
                *(uint4*)(smem + OFF_B0_LO + off) =
                    make_uint4(lo[4 * j], lo[4 * j + 1], lo[4 * j + 2], lo[4 * j + 3]);
            }
        }
        __syncthreads();

        // ---- A1 copy to out + zero scratch cols 128..319 ----
        for (int idx = tid; idx < TN * 192; idx += NTHREADS) {
            int e = idx / 192, k = idx % 192;
            int n = nbase + e;
            if (n < NN) {
                u64 off = (u64)n * FEAT + 128 + k;
                out[off] = g_A[off];
                g_A[off] = 0.f;
            }
        }

        // ---- MMA: mix0[64n,128c] = B0 @ Wm^T, split-bf16 3-pass ----
        float acc[4][4];
#pragma unroll
        for (int b = 0; b < 4; b++)
#pragma unroll
            for (int c = 0; c < 4; c++) acc[b][c] = 0.f;
#pragma unroll
        for (int k = 0; k < 12; k++) {
            int g0 = 2 * k;
            u32 ah[4], al[4];
            lda(ah, sb + OFF_B0_HI, wm * 16, g0, lane, 384);
            lda(al, sb + OFF_B0_LO, wm * 16, g0, lane, 384);
#pragma unroll
            for (int np = 0; np < 2; np++) {
                u32 bh[4], bl[4];
                ldb(bh, sb + OFF_WM_HI, wn * 32 + np * 16, g0, lane, 384);
                ldb(bl, sb + OFF_WM_LO, wn * 32 + np * 16, g0, lane, 384);
                mma16816(acc[2 * np],     ah, bh[0], bh[1]);
                mma16816(acc[2 * np + 1], ah, bh[2], bh[3]);
                mma16816(acc[2 * np],     al, bh[0], bh[1]);
                mma16816(acc[2 * np + 1], al, bh[2], bh[3]);
                mma16816(acc[2 * np],     ah, bl[0], bl[1]);
                mma16816(acc[2 * np + 1], ah, bl[2], bl[3]);
            }
        }

        // ---- readout: out[:, :128] = A0 + mix0; zero scratch A0 ----
        {
            int row0 = nbase + wm * 16 + gq;
            int row1 = row0 + 8;
#pragma unroll
            for (int nt = 0; nt < 4; nt++) {
                int col = wn * 32 + nt * 8 + 2 * tq;
                if (row0 < NN) {
                    u64 off = (u64)row0 * FEAT + col;
                    float2 A0v = *(const float2*)&g_A[off];
                    *(float2*)&out[off] = make_float2(A0v.x + acc[nt][0], A0v.y + acc[nt][1]);
                    *(float2*)&g_A[off] = make_float2(0.f, 0.f);
                }
                if (row1 < NN) {
                    u64 off = (u64)row1 * FEAT + col;
                    float2 A0v = *(const float2*)&g_A[off];
                    *(float2*)&out[off] = make_float2(A0v.x + acc[nt][2], A0v.y + acc[nt][3]);
                    *(float2*)&g_A[off] = make_float2(0.f, 0.f);
                }
            }
        }
        __syncthreads();
    }

    // ---- reset barrier counters (last block out) ----
    __syncthreads();
    if (tid == 0) {
        __threadfence();
        unsigned d = atomicAdd(&g_depart, 1u);
        if (d == (unsigned)gridDim.x - 1) {
            g_arrive = 0;
            g_depart = 0;
            __threadfence();
        }
    }
}

extern "C" void kernel_launch(void* const* d_in, const int* in_sizes, int n_in,
                              void* d_out, int out_size) {
    const float* node_attrs = (const float*)d_in[0];
    const int*   edge_index = (const int*)d_in[1];
    const float* edge_vec   = (const float*)d_in[2];
    const float* edge_len   = (const float*)d_in[3];
    const float* W1         = (const float*)d_in[4];
    const float* W2         = (const float*)d_in[5];
    const float* Wtp0       = (const float*)d_in[6];
    const float* Wtp1       = (const float*)d_in[7];
    const float* Wmix0      = (const float*)d_in[8];
    float* out = (float*)d_out;

    cudaFuncSetAttribute(ace_fused_kernel, cudaFuncAttributeMaxDynamicSharedMemorySize, SMEM_BYTES);

    ace_fused_kernel<<<NBLOCKS, NTHREADS, SMEM_BYTES>>>(
        node_attrs, edge_index, edge_vec, edge_len, W1, W2, Wtp0, Wtp1, Wmix0, out);
}

// round 16
// speedup vs baseline: 1.1125x; 1.0254x over previous
#include <cuda_runtime.h>
#include <cuda_bf16.h>
#include <math.h>

#define NN 50000
#define NE 400000
#define HID 128
#define FEAT 320
#define TEDGE 128
#define TN 64
#define NTHREADS 512
#define NBLOCKS 148

typedef unsigned long long u64;
typedef unsigned int u32;

// ---------------- smem byte offsets (edge phase) ----------------
#define OFF_WC_HI   0         // WC^T [192n][128k] bf16, 256B rows, swizzled
#define OFF_WC_LO   49152
#define OFF_W2_HI   98304     // W2^T [128c][64j] bf16, 128B rows
#define OFF_W2_LO   114688
#define OFF_NF_HI   131072    // nf [128e][128k] bf16, 256B rows
#define OFF_NF_LO   163840
#define OFF_H_HI    131072    // h [128e][64j] overlays NF_HI (dead after MMA C)
#define OFF_H_LO    147456
#define OFF_RAD     196608    // 128*9 floats
#define OFF_Y1      201216    // 128*4 floats
#define OFF_W1S     203264    // 512 floats
#define OFF_SND     205312
#define OFF_RCV     205824
#define SMEM_BYTES  206336
// node phase overlays: WM_HI @0 (48KB), WM_LO @49152 (48KB)  [dead WC region]
//                      B0_HI @131072 (24KB), B0_LO @155648 (24KB) [dead NF region]
#define OFF_WM_HI   0
#define OFF_WM_LO   49152
#define OFF_B0_HI   131072
#define OFF_B0_LO   155648

__device__ float g_A[(size_t)NN * FEAT];
__device__ unsigned int g_arrive;
__device__ unsigned int g_depart;

__device__ __forceinline__ u64 pack2(float a, float b) {
    u64 r; asm("mov.b64 %0, {%1,%2};" : "=l"(r) : "f"(a), "f"(b)); return r;
}
__device__ __forceinline__ void unpack2(u64 v, float& a, float& b) {
    asm("mov.b64 {%0,%1}, %2;" : "=f"(a), "=f"(b) : "l"(v));
}
__device__ __forceinline__ void red4(float* p, float a, float b, float c, float d) {
    asm volatile("red.global.add.v4.f32 [%0], {%1,%2,%3,%4};"
                 :: "l"(p), "f"(a), "f"(b), "f"(c), "f"(d) : "memory");
}
__device__ __forceinline__ void red2(float* p, float a, float b) {
    asm volatile("red.global.add.v2.f32 [%0], {%1,%2};"
                 :: "l"(p), "f"(a), "f"(b) : "memory");
}
__device__ __forceinline__ u32 smem_u32_of(const void* p) {
    u32 a; asm("{ .reg .u64 t; cvta.to.shared.u64 t, %1; cvt.u32.u64 %0, t; }"
               : "=r"(a) : "l"(p));
    return a;
}
__device__ __forceinline__ u32 prmt7632(u32 a, u32 b) {
    u32 d; asm("prmt.b32 %0,%1,%2,0x7632;" : "=r"(d) : "r"(a), "r"(b)); return d;
}
__device__ __forceinline__ u32 cvt_bf2(float lo, float hi) {
    u32 d; asm("cvt.rn.bf16x2.f32 %0, %1, %2;" : "=r"(d) : "f"(hi), "f"(lo)); return d;
}
__device__ __forceinline__ void split2(float a, float b, u32& h, u32& l) {
    u32 au = __float_as_uint(a), bu = __float_as_uint(b);
    h = prmt7632(au, bu);
    l = cvt_bf2(a - __uint_as_float(au & 0xFFFF0000u),
                b - __uint_as_float(bu & 0xFFFF0000u));
}
__device__ __forceinline__ u32 swz(int row, int granule, int stride) {
    return (u32)(row * stride + (((granule ^ (row & 7)) << 4)));
}
__device__ __forceinline__ void lda(u32* f, u32 base, int R, int g0, int lane, int stride) {
    int row = R + (lane & 15);
    int g = g0 + (lane >> 4);
    u32 addr = base + swz(row, g, stride);
    asm volatile("ldmatrix.sync.aligned.m8n8.x4.shared.b16 {%0,%1,%2,%3}, [%4];"
                 : "=r"(f[0]), "=r"(f[1]), "=r"(f[2]), "=r"(f[3]) : "r"(addr));
}
__device__ __forceinline__ void ldb(u32* f, u32 base, int N0, int g0, int lane, int stride) {
    int n = N0 + (lane & 7) + ((lane >> 4) << 3);
    int g = g0 + ((lane >> 3) & 1);
    u32 addr = base + swz(n, g, stride);
    asm volatile("ldmatrix.sync.aligned.m8n8.x4.shared.b16 {%0,%1,%2,%3}, [%4];"
                 : "=r"(f[0]), "=r"(f[1]), "=r"(f[2]), "=r"(f[3]) : "r"(addr));
}
__device__ __forceinline__ void mma16816(float* d, const u32* a, u32 b0, u32 b1) {
    asm volatile("mma.sync.aligned.m16n8k16.row.col.f32.bf16.bf16.f32 "
                 "{%0,%1,%2,%3}, {%4,%5,%6,%7}, {%8,%9}, {%0,%1,%2,%3};"
                 : "+f"(d[0]), "+f"(d[1]), "+f"(d[2]), "+f"(d[3])
                 : "r"(a[0]), "r"(a[1]), "r"(a[2]), "r"(a[3]), "r"(b0), "r"(b1));
}

__global__ void __launch_bounds__(NTHREADS, 1)
ace_fused_kernel(const float* __restrict__ node_attrs,
                 const int* __restrict__ edge_index,
                 const float* __restrict__ edge_vec,
                 const float* __restrict__ edge_len,
                 const float* __restrict__ W1,
                 const float* __restrict__ W2,
                 const float* __restrict__ Wtp0,
                 const float* __restrict__ Wtp1,
                 const float* __restrict__ Wmix0,
                 float* __restrict__ out) {
    extern __shared__ char smem[];
    float* radS = (float*)(smem + OFF_RAD);
    float* y1S  = (float*)(smem + OFF_Y1);
    float* W1s  = (float*)(smem + OFF_W1S);
    int*   sndS = (int*)(smem + OFF_SND);
    int*   rcvS = (int*)(smem + OFF_RCV);

    const int tid = threadIdx.x;
    const int lane = tid & 31;
    const int wid = tid >> 5;
    const u32 sb = smem_u32_of(smem);

    // ---- stage weights: split bf16 hi/lo, swizzled ----
    for (int i = tid; i < 512; i += NTHREADS) W1s[i] = W1[i];
    for (int i = tid; i < 128 * 64; i += NTHREADS) {
        int c = i >> 6, j = i & 63;
        float v = W2[j * 128 + c];
        u32 vu = __float_as_uint(v);
        u32 off = swz(c, j >> 3, 128) + (j & 7) * 2;
        *(unsigned short*)(smem + OFF_W2_HI + off) = (unsigned short)(vu >> 16);
        *(__nv_bfloat16*)(smem + OFF_W2_LO + off) =
            __float2bfloat16(v - __uint_as_float(vu & 0xFFFF0000u));
    }
    for (int i = tid; i < 192 * 128; i += NTHREADS) {
        int n = i >> 7, k = i & 127;
        float v = (n < 128) ? Wtp0[k * 128 + n] : Wtp1[k * 64 + (n - 128)];
        u32 vu = __float_as_uint(v);
        u32 off = swz(n, k >> 3, 256) + (k & 7) * 2;
        *(unsigned short*)(smem + OFF_WC_HI + off) = (unsigned short)(vu >> 16);
        *(__nv_bfloat16*)(smem + OFF_WC_LO + off) =
            __float2bfloat16(v - __uint_as_float(vu & 0xFFFF0000u));
    }
    __syncthreads();

    const int wm = wid & 3;   // row group
    const int wn = wid >> 2;  // col group
    const int tq = lane & 3;  // quad thread
    const int gq = lane >> 2; // group row

    // ================= EDGE PHASE =================
    const int ntiles = NE / TEDGE;  // 3125
    for (int tile = blockIdx.x; tile < ntiles; tile += gridDim.x) {
        const int ebase = tile * TEDGE;

        // ---- Phase A: radials distributed over ALL threads (2 per thread, fast paths) ----
        {
            int e = tid >> 2;              // 0..127
            int rr = (tid & 3) * 2;        // radials rr, rr+1
            float x = edge_len[ebase + e];
            bool valid = (x > 0.f) && (x < 5.0f);
            float pref = valid ? __fdividef(0.22360679774997896f, x) : 0.f;
            radS[e * 9 + rr]     = pref * __sinf((float)(rr + 1) * 0.6283185307179586f * x);
            radS[e * 9 + rr + 1] = pref * __sinf((float)(rr + 2) * 0.6283185307179586f * x);
        }
        if (tid < TEDGE) {
            int e = ebase + tid;
            float vx = edge_vec[e * 3 + 0];
            float vy = edge_vec[e * 3 + 1];
            float vz = edge_vec[e * 3 + 2];
            float rn = rsqrtf(vx * vx + vy * vy + vz * vz) * 1.7320508075688772f;
            y1S[tid * 4 + 0] = vy * rn;
            y1S[tid * 4 + 1] = vz * rn;
            y1S[tid * 4 + 2] = vx * rn;
            sndS[tid] = edge_index[e];
            rcvS[tid] = edge_index[NE + e];
        }
        __syncthreads();

        // ---- Phase B: h = 0.018552463*silu(rad@W1), fast div, split bf16 ----
        {
            int e = tid >> 2;
            int j0 = (tid & 3) << 4;
            float hv[16];
#pragma unroll
            for (int i = 0; i < 16; i++) {
                float s = 0.f;
#pragma unroll
                for (int r = 0; r < 8; r++)
                    s += radS[e * 9 + r] * W1s[r * 64 + j0 + i];
                hv[i] = 0.018552463f * __fdividef(s, 1.f + __expf(-s));
            }
            u32 hi[8], lo[8];
#pragma unroll
            for (int q = 0; q < 8; q++) split2(hv[2 * q], hv[2 * q + 1], hi[q], lo[q]);
            int x = j0 >> 3;
            u32 o0 = swz(e, x, 128), o1 = swz(e, x + 1, 128);
            *(uint4*)(smem + OFF_H_HI + o0) = make_uint4(hi[0], hi[1], hi[2], hi[3]);
            *(uint4*)(smem + OFF_H_HI + o1) = make_uint4(hi[4], hi[5], hi[6], hi[7]);
            *(uint4*)(smem + OFF_H_LO + o0) = make_uint4(lo[0], lo[1], lo[2], lo[3]);
            *(uint4*)(smem + OFF_H_LO + o1) = make_uint4(lo[4], lo[5], lo[6], lo[7]);
        }
        __syncthreads();

        // ---- MMA C: R_n[128e,128c] = h @ W2^T, split-bf16 3-pass ----
        float accc[2][4][4];
#pragma unroll
        for (int a = 0; a < 2; a++)
#pragma unroll
            for (int b = 0; b < 4; b++)
#pragma unroll
                for (int c = 0; c < 4; c++) accc[a][b][c] = 0.f;
#pragma unroll
        for (int k = 0; k < 4; k++) {
            int g0 = 2 * k;
            u32 ah0[4], ah1[4], al0[4], al1[4];
            lda(ah0, sb + OFF_H_HI, wm * 32,      g0, lane, 128);
            lda(ah1, sb + OFF_H_HI, wm * 32 + 16, g0, lane, 128);
            lda(al0, sb + OFF_H_LO, wm * 32,      g0, lane, 128);
            lda(al1, sb + OFF_H_LO, wm * 32 + 16, g0, lane, 128);
#pragma unroll
            for (int np = 0; np < 2; np++) {
                u32 bh[4], bl[4];
                ldb(bh, sb + OFF_W2_HI, wn * 32 + np * 16, g0, lane, 128);
                ldb(bl, sb + OFF_W2_LO, wn * 32 + np * 16, g0, lane, 128);
                mma16816(accc[0][2 * np],     ah0, bh[0], bh[1]);
                mma16816(accc[0][2 * np + 1], ah0, bh[2], bh[3]);
                mma16816(accc[1][2 * np],     ah1, bh[0], bh[1]);
                mma16816(accc[1][2 * np + 1], ah1, bh[2], bh[3]);
                mma16816(accc[0][2 * np],     al0, bh[0], bh[1]);
                mma16816(accc[0][2 * np + 1], al0, bh[2], bh[3]);
                mma16816(accc[1][2 * np],     al1, bh[0], bh[1]);
                mma16816(accc[1][2 * np + 1], al1, bh[2], bh[3]);
                mma16816(accc[0][2 * np],     ah0, bl[0], bl[1]);
                mma16816(accc[0][2 * np + 1], ah0, bl[2], bl[3]);
                mma16816(accc[1][2 * np],     ah1, bl[0], bl[1]);
                mma16816(accc[1][2 * np + 1], ah1, bl[2], bl[3]);
            }
        }
        __syncthreads();

        // ---- readout C: gather + multiply + split + store ----
#pragma unroll
        for (int mt = 0; mt < 2; mt++) {
            int r0 = wm * 32 + mt * 16 + gq;
            int r1 = r0 + 8;
            int s0 = sndS[r0], s1 = sndS[r1];
#pragma unroll
            for (int nt = 0; nt < 4; nt++) {
                int col = wn * 32 + nt * 8 + 2 * tq;
                float2 a0 = *(const float2*)&node_attrs[(u64)s0 * HID + col];
                float2 a1 = *(const float2*)&node_attrs[(u64)s1 * HID + col];
                float v00 = accc[mt][nt][0] * a0.x, v01 = accc[mt][nt][1] * a0.y;
                float v10 = accc[mt][nt][2] * a1.x, v11 = accc[mt][nt][3] * a1.y;
                u32 h0, l0, h1, l1;
                split2(v00, v01, h0, l0);
                split2(v10, v11, h1, l1);
                u32 o0 = swz(r0, col >> 3, 256) + (col & 7) * 2;
                u32 o1 = swz(r1, col >> 3, 256) + (col & 7) * 2;
                *(u32*)(smem + OFF_NF_HI + o0) = h0;
                *(u32*)(smem + OFF_NF_LO + o0) = l0;
                *(u32*)(smem + OFF_NF_HI + o1) = h1;
                *(u32*)(smem + OFF_NF_LO + o1) = l1;
            }
        }
        __syncthreads();

        float accd[2][6][4];
#pragma unroll
        for (int a = 0; a < 2; a++)
#pragma unroll
            for (int b = 0; b < 6; b++)
#pragma unroll
                for (int c = 0; c < 4; c++) accd[a][b][c] = 0.f;
        const int NB = wn * 48;
#pragma unroll
        for (int k = 0; k < 8; k++) {
            int g0 = 2 * k;
            u32 ah0[4], ah1[4], al0[4], al1[4];
            lda(ah0, sb + OFF_NF_HI, wm * 32,      g0, lane, 256);
            lda(ah1, sb + OFF_NF_HI, wm * 32 + 16, g0, lane, 256);
            lda(al0, sb + OFF_NF_LO, wm * 32,      g0, lane, 256);
            lda(al1, sb + OFF_NF_LO, wm * 32 + 16, g0, lane, 256);
#pragma unroll
            for (int np = 0; np < 3; np++) {
                u32 bh[4], bl[4];
                ldb(bh, sb + OFF_WC_HI, NB + np * 16, g0, lane, 256);
                ldb(bl, sb + OFF_WC_LO, NB + np * 16, g0, lane, 256);
                mma16816(accd[0][2 * np],     ah0, bh[0], bh[1]);
                mma16816(accd[0][2 * np + 1], ah0, bh[2], bh[3]);
                mma16816(accd[1][2 * np],     ah1, bh[0], bh[1]);
                mma16816(accd[1][2 * np + 1], ah1, bh[2], bh[3]);
                mma16816(accd[0][2 * np],     al0, bh[0], bh[1]);
                mma16816(accd[0][2 * np + 1], al0, bh[2], bh[3]);
                mma16816(accd[1][2 * np],     al1, bh[0], bh[1]);
                mma16816(accd[1][2 * np + 1], al1, bh[2], bh[3]);
                mma16816(accd[0][2 * np],     ah0, bl[0], bl[1]);
                mma16816(accd[0][2 * np + 1], ah0, bl[2], bl[3]);
                mma16816(accd[1][2 * np],     ah1, bl[0], bl[1]);
                mma16816(accd[1][2 * np + 1], ah1, bl[2], bl[3]);
            }
        }

        // ---- scatter: quad-pair merge via shfl -> red4 ----
#pragma unroll
        for (int mt = 0; mt < 2; mt++) {
            int r0 = wm * 32 + mt * 16 + gq;
            int r1 = r0 + 8;
            int myrow = (tq & 1) ? r1 : r0;
            float* gp = g_A + (u64)rcvS[myrow] * FEAT;
            float y0 = y1S[myrow * 4 + 0];
            float y1v = y1S[myrow * 4 + 1];
            float y2 = y1S[myrow * 4 + 2];
#pragma unroll
            for (int nt = 0; nt < 6; nt++) {
                u64 up0 = pack2(accd[mt][nt][0], accd[mt][nt][1]);
                u64 up1 = pack2(accd[mt][nt][2], accd[mt][nt][3]);
                u64 q0 = __shfl_xor_sync(0xffffffffu, up0, 1);
                u64 q1 = __shfl_xor_sync(0xffffffffu, up1, 1);
                float a0, a1, b0, b1;
                if ((tq & 1) == 0) {
                    unpack2(up0, a0, a1);
                    unpack2(q0, b0, b1);
                } else {
                    unpack2(q1, a0, a1);
                    unpack2(up1, b0, b1);
                }
                int colb = NB + nt * 8 + ((tq >> 1) << 2);
                if (colb < 128) {
                    red4(gp + colb, a0, a1, b0, b1);
                } else {
                    int m0 = colb - 128;
                    float* p = gp + 128 + m0 * 3;
                    float v0 = a0 * y0, v1 = a0 * y1v, v2 = a0 * y2;
                    float v3 = a1 * y0, v4 = a1 * y1v, v5 = a1 * y2;
                    float v6 = b0 * y0, v7 = b0 * y1v, v8 = b0 * y2;
                    float v9 = b1 * y0, v10 = b1 * y1v, v11 = b1 * y2;
                    if ((m0 & 2) == 0) {
                        red4(p, v0, v1, v2, v3);
                        red4(p + 4, v4, v5, v6, v7);
                        red4(p + 8, v8, v9, v10, v11);
                    } else {
                        red2(p, v0, v1);
                        red4(p + 2, v2, v3, v4, v5);
                        red4(p + 6, v6, v7, v8, v9);
                        red2(p + 10, v10, v11);
                    }
                }
            }
        }
        __syncthreads();
    }

    // ================= GRID BARRIER =================
    __threadfence();
    __syncthreads();
    if (tid == 0) {
        atomicAdd(&g_arrive, 1u);
        while (*(volatile unsigned int*)&g_arrive < (unsigned)gridDim.x)
            __nanosleep(128);
    }
    __syncthreads();
    __threadfence();

    // ================= NODE PHASE (split-bf16 HMMA) =================
    const float s_mix = 0.07216878364870323f;  // 1/sqrt(192)
    for (int i = tid; i < 128 * 192; i += NTHREADS) {
        int c = i / 192, k = i % 192;
        float v = Wmix0[k * 128 + c] * s_mix;
        u32 vu = __float_as_uint(v);
        u32 off = swz(c, k >> 3, 384) + (k & 7) * 2;
        *(unsigned short*)(smem + OFF_WM_HI + off) = (unsigned short)(vu >> 16);
        *(__nv_bfloat16*)(smem + OFF_WM_LO + off) =
            __float2bfloat16(v - __uint_as_float(vu & 0xFFFF0000u));
    }
    __syncthreads();

    const int ntilesN = (NN + TN - 1) / TN;  // 782
    for (int tile = blockIdx.x; tile < ntilesN; tile += gridDim.x) {
        const int nbase = tile * TN;

        // ---- build B0 split tiles [64n][192k] bf16 hi/lo ----
        {
            int n = tid >> 3;            // 0..63
            int k0 = (tid & 7) * 24;     // 24 consecutive k per thread
            int ng = nbase + n;
            float v[24];
            if (ng < NN) {
                const float* gp = g_A + (u64)ng * FEAT;
#pragma unroll
                for (int i = 0; i < 24; i++) {
                    int k = k0 + i;
                    if (k < 128) {
                        float a = gp[k];
                        v[i] = a * a;
                    } else {
                        int m = k - 128;
                        float q0 = gp[128 + m * 3], q1 = gp[128 + m * 3 + 1], q2 = gp[128 + m * 3 + 2];
                        v[i] = (q0 * q0 + q1 * q1 + q2 * q2) * 0.5773502691896258f;
                    }
                }
            } else {
#pragma unroll
                for (int i = 0; i < 24; i++) v[i] = 0.f;
            }
            u32 hi[12], lo[12];
#pragma unroll
            for (int q = 0; q < 12; q++) split2(v[2 * q], v[2 * q + 1], hi[q], lo[q]);
            int gbase = 3 * (tid & 7);
#pragma unroll
            for (int j = 0; j < 3; j++) {
                u32 off = swz(n, gbase + j, 384);
                *(uint4*)(smem + OFF_B0_HI + off) =
                    make_uint4(hi[4 * j], hi[4 * j + 1], hi[4 * j + 2], hi[4 * j + 3]);
                *(uint4*)(smem + OFF_B0_LO + off) =
                    make_uint4(lo[4 * j], lo[4 * j + 1], lo[4 * j + 2], lo[4 * j + 3]);
            }
        }
        __syncthreads();

        // ---- A1 copy to out + zero scratch cols 128..319 ----
        for (int idx = tid; idx < TN * 192; idx += NTHREADS) {
            int e = idx / 192, k = idx % 192;
            int n = nbase + e;
            if (n < NN) {
                u64 off = (u64)n * FEAT + 128 + k;
                out[off] = g_A[off];
                g_A[off] = 0.f;
            }
        }

        // ---- MMA: mix0[64n,128c] = B0 @ Wm^T, split-bf16 3-pass ----
        float acc[4][4];
#pragma unroll
        for (int b = 0; b < 4; b++)
#pragma unroll
            for (int c = 0; c < 4; c++) acc[b][c] = 0.f;
#pragma unroll
        for (int k = 0; k < 12; k++) {
            int g0 = 2 * k;
            u32 ah[4], al[4];
            lda(ah, sb + OFF_B0_HI, wm * 16, g0, lane, 384);
            lda(al, sb + OFF_B0_LO, wm * 16, g0, lane, 384);
#pragma unroll
            for (int np = 0; np < 2; np++) {
                u32 bh[4], bl[4];
                ldb(bh, sb + OFF_WM_HI, wn * 32 + np * 16, g0, lane, 384);
                ldb(bl, sb + OFF_WM_LO, wn * 32 + np * 16, g0, lane, 384);
                mma16816(acc[2 * np],     ah, bh[0], bh[1]);
                mma16816(acc[2 * np + 1], ah, bh[2], bh[3]);
                mma16816(acc[2 * np],     al, bh[0], bh[1]);
                mma16816(acc[2 * np + 1], al, bh[2], bh[3]);
                mma16816(acc[2 * np],     ah, bl[0], bl[1]);
                mma16816(acc[2 * np + 1], ah, bl[2], bl[3]);
            }
        }

        // ---- readout: out[:, :128] = A0 + mix0; zero scratch A0 ----
        {
            int row0 = nbase + wm * 16 + gq;
            int row1 = row0 + 8;
#pragma unroll
            for (int nt = 0; nt < 4; nt++) {
                int col = wn * 32 + nt * 8 + 2 * tq;
                if (row0 < NN) {
                    u64 off = (u64)row0 * FEAT + col;
                    float2 A0v = *(const float2*)&g_A[off];
                    *(float2*)&out[off] = make_float2(A0v.x + acc[nt][0], A0v.y + acc[nt][1]);
                    *(float2*)&g_A[off] = make_float2(0.f, 0.f);
                }
                if (row1 < NN) {
                    u64 off = (u64)row1 * FEAT + col;
                    float2 A0v = *(const float2*)&g_A[off];
                    *(float2*)&out[off] = make_float2(A0v.x + acc[nt][2], A0v.y + acc[nt][3]);
                    *(float2*)&g_A[off] = make_float2(0.f, 0.f);
                }
            }
        }
        __syncthreads();
    }

    // ---- reset barrier counters (last block out) ----
    __syncthreads();
    if (tid == 0) {
        __threadfence();
        unsigned d = atomicAdd(&g_depart, 1u);
        if (d == (unsigned)gridDim.x - 1) {
            g_arrive = 0;
            g_depart = 0;
            __threadfence();
        }
    }
}

extern "C" void kernel_launch(void* const* d_in, const int* in_sizes, int n_in,
                              void* d_out, int out_size) {
    const float* node_attrs = (const float*)d_in[0];
    const int*   edge_index = (const int*)d_in[1];
    const float* edge_vec   = (const float*)d_in[2];
    const float* edge_len   = (const float*)d_in[3];
    const float* W1         = (const float*)d_in[4];
    const float* W2         = (const float*)d_in[5];
    const float* Wtp0       = (const float*)d_in[6];
    const float* Wtp1       = (const float*)d_in[7];
    const float* Wmix0      = (const float*)d_in[8];
    float* out = (float*)d_out;

    cudaFuncSetAttribute(ace_fused_kernel, cudaFuncAttributeMaxDynamicSharedMemorySize, SMEM_BYTES);

    ace_fused_kernel<<<NBLOCKS, NTHREADS, SMEM_BYTES>>>(
        node_attrs, edge_index, edge_vec, edge_len, W1, W2, Wtp0, Wtp1, Wmix0, out);
}

// round 17
// speedup vs baseline: 1.1599x; 1.0426x over previous
#include <cuda_runtime.h>
#include <cuda_bf16.h>
#include <math.h>

#define NN 50000
#define NE 400000
#define HID 128
#define FEAT 320
#define TEDGE 128
#define TN 64
#define NTHREADS 512
#define NBLOCKS 148

typedef unsigned long long u64;
typedef unsigned int u32;

// ---------------- smem byte offsets (edge phase) ----------------
#define OFF_WC_HI   0         // WC^T [192n][128k] bf16, 256B rows, swizzled
#define OFF_WC_LO   49152
#define OFF_W2_HI   98304     // W2^T [128c][64j] bf16, 128B rows
#define OFF_W2_LO   114688
#define OFF_NF_HI   131072    // nf [128e][128k] bf16, 256B rows
#define OFF_NF_LO   163840
#define OFF_H_HI    131072    // h [128e][64j] overlays NF_HI (dead after MMA C)
#define OFF_H_LO    147456
#define OFF_RAD     196608    // 128*9 floats
#define OFF_Y1      201216    // 128*4 floats
#define OFF_W1S     203264    // 512 floats
#define OFF_SND     205312
#define OFF_RCV     205824
#define SMEM_BYTES  206336
// node phase overlays
#define OFF_WM_HI   0
#define OFF_WM_LO   49152
#define OFF_B0_HI   131072
#define OFF_B0_LO   155648

__device__ float g_A[(size_t)NN * FEAT];
__device__ unsigned int g_arrive;
__device__ unsigned int g_depart;

__device__ __forceinline__ u64 pack2(float a, float b) {
    u64 r; asm("mov.b64 %0, {%1,%2};" : "=l"(r) : "f"(a), "f"(b)); return r;
}
__device__ __forceinline__ void unpack2(u64 v, float& a, float& b) {
    asm("mov.b64 {%0,%1}, %2;" : "=f"(a), "=f"(b) : "l"(v));
}
__device__ __forceinline__ void red4(float* p, float a, float b, float c, float d) {
    asm volatile("red.global.add.v4.f32 [%0], {%1,%2,%3,%4};"
                 :: "l"(p), "f"(a), "f"(b), "f"(c), "f"(d) : "memory");
}
__device__ __forceinline__ void red2(float* p, float a, float b) {
    asm volatile("red.global.add.v2.f32 [%0], {%1,%2};"
                 :: "l"(p), "f"(a), "f"(b) : "memory");
}
__device__ __forceinline__ u32 smem_u32_of(const void* p) {
    u32 a; asm("{ .reg .u64 t; cvta.to.shared.u64 t, %1; cvt.u32.u64 %0, t; }"
               : "=r"(a) : "l"(p));
    return a;
}
__device__ __forceinline__ u32 prmt7632(u32 a, u32 b) {
    u32 d; asm("prmt.b32 %0,%1,%2,0x7632;" : "=r"(d) : "r"(a), "r"(b)); return d;
}
__device__ __forceinline__ u32 cvt_bf2(float lo, float hi) {
    u32 d; asm("cvt.rn.bf16x2.f32 %0, %1, %2;" : "=r"(d) : "f"(hi), "f"(lo)); return d;
}
__device__ __forceinline__ void split2(float a, float b, u32& h, u32& l) {
    u32 au = __float_as_uint(a), bu = __float_as_uint(b);
    h = prmt7632(au, bu);
    l = cvt_bf2(a - __uint_as_float(au & 0xFFFF0000u),
                b - __uint_as_float(bu & 0xFFFF0000u));
}
__device__ __forceinline__ u32 swz(int row, int granule, int stride) {
    return (u32)(row * stride + (((granule ^ (row & 7)) << 4)));
}
__device__ __forceinline__ void lda(u32* f, u32 base, int R, int g0, int lane, int stride) {
    int row = R + (lane & 15);
    int g = g0 + (lane >> 4);
    u32 addr = base + swz(row, g, stride);
    asm volatile("ldmatrix.sync.aligned.m8n8.x4.shared.b16 {%0,%1,%2,%3}, [%4];"
                 : "=r"(f[0]), "=r"(f[1]), "=r"(f[2]), "=r"(f[3]) : "r"(addr));
}
__device__ __forceinline__ void ldb(u32* f, u32 base, int N0, int g0, int lane, int stride) {
    int n = N0 + (lane & 7) + ((lane >> 4) << 3);
    int g = g0 + ((lane >> 3) & 1);
    u32 addr = base + swz(n, g, stride);
    asm volatile("ldmatrix.sync.aligned.m8n8.x4.shared.b16 {%0,%1,%2,%3}, [%4];"
                 : "=r"(f[0]), "=r"(f[1]), "=r"(f[2]), "=r"(f[3]) : "r"(addr));
}
__device__ __forceinline__ void mma16816(float* d, const u32* a, u32 b0, u32 b1) {
    asm volatile("mma.sync.aligned.m16n8k16.row.col.f32.bf16.bf16.f32 "
                 "{%0,%1,%2,%3}, {%4,%5,%6,%7}, {%8,%9}, {%0,%1,%2,%3};"
                 : "+f"(d[0]), "+f"(d[1]), "+f"(d[2]), "+f"(d[3])
                 : "r"(a[0]), "r"(a[1]), "r"(a[2]), "r"(a[3]), "r"(b0), "r"(b1));
}
__device__ __forceinline__ void barg(int id) {
    asm volatile("bar.sync %0, 128;" :: "r"(id) : "memory");
}

__global__ void __launch_bounds__(NTHREADS, 1)
ace_fused_kernel(const float* __restrict__ node_attrs,
                 const int* __restrict__ edge_index,
                 const float* __restrict__ edge_vec,
                 const float* __restrict__ edge_len,
                 const float* __restrict__ W1,
                 const float* __restrict__ W2,
                 const float* __restrict__ Wtp0,
                 const float* __restrict__ Wtp1,
                 const float* __restrict__ Wmix0,
                 float* __restrict__ out) {
    extern __shared__ char smem[];
    float* radS = (float*)(smem + OFF_RAD);
    float* y1S  = (float*)(smem + OFF_Y1);
    float* W1s  = (float*)(smem + OFF_W1S);
    int*   sndS = (int*)(smem + OFF_SND);
    int*   rcvS = (int*)(smem + OFF_RCV);

    const int tid = threadIdx.x;
    const int lane = tid & 31;
    const int wid = tid >> 5;
    const u32 sb = smem_u32_of(smem);

    // ---- stage weights: split bf16 hi/lo, swizzled ----
    for (int i = tid; i < 512; i += NTHREADS) W1s[i] = W1[i];
    for (int i = tid; i < 128 * 64; i += NTHREADS) {
        int c = i >> 6, j = i & 63;
        float v = W2[j * 128 + c];
        u32 vu = __float_as_uint(v);
        u32 off = swz(c, j >> 3, 128) + (j & 7) * 2;
        *(unsigned short*)(smem + OFF_W2_HI + off) = (unsigned short)(vu >> 16);
        *(__nv_bfloat16*)(smem + OFF_W2_LO + off) =
            __float2bfloat16(v - __uint_as_float(vu & 0xFFFF0000u));
    }
    for (int i = tid; i < 192 * 128; i += NTHREADS) {
        int n = i >> 7, k = i & 127;
        float v = (n < 128) ? Wtp0[k * 128 + n] : Wtp1[k * 64 + (n - 128)];
        u32 vu = __float_as_uint(v);
        u32 off = swz(n, k >> 3, 256) + (k & 7) * 2;
        *(unsigned short*)(smem + OFF_WC_HI + off) = (unsigned short)(vu >> 16);
        *(__nv_bfloat16*)(smem + OFF_WC_LO + off) =
            __float2bfloat16(v - __uint_as_float(vu & 0xFFFF0000u));
    }
    __syncthreads();

    const int wm = wid & 3;   // row group
    const int wn = wid >> 2;  // col group
    const int tq = lane & 3;  // quad thread
    const int gq = lane >> 2; // group row
    const int gbar = 1 + wm;  // named barrier per wm-group (128 threads)

    // ================= EDGE PHASE =================
    const int ntiles = NE / TEDGE;  // 3125
    // Phase-A prefetch registers
    float pX = 1.f, pVx = 0.f, pVy = 0.f, pVz = 1.f;
    int pS = 0, pR = 0;
    {
        int t0 = blockIdx.x;
        if (t0 < ntiles) {
            pX = edge_len[t0 * TEDGE + (tid >> 2)];
            if (tid < TEDGE) {
                int e = t0 * TEDGE + tid;
                pVx = edge_vec[e * 3 + 0];
                pVy = edge_vec[e * 3 + 1];
                pVz = edge_vec[e * 3 + 2];
                pS = edge_index[e];
                pR = edge_index[NE + e];
            }
        }
    }

    for (int tile = blockIdx.x; tile < ntiles; tile += gridDim.x) {
        // ---- Phase A: per-edge scalars (from prefetched regs) ----
        {
            int e = tid >> 2;              // 0..127
            int rr = (tid & 3) * 2;        // radials rr, rr+1
            float x = pX;
            bool valid = (x > 0.f) && (x < 5.0f);
            float pref = valid ? __fdividef(0.22360679774997896f, x) : 0.f;
            radS[e * 9 + rr]     = pref * __sinf((float)(rr + 1) * 0.6283185307179586f * x);
            radS[e * 9 + rr + 1] = pref * __sinf((float)(rr + 2) * 0.6283185307179586f * x);
        }
        if (tid < TEDGE) {
            float rn = rsqrtf(pVx * pVx + pVy * pVy + pVz * pVz) * 1.7320508075688772f;
            y1S[tid * 4 + 0] = pVy * rn;
            y1S[tid * 4 + 1] = pVz * rn;
            y1S[tid * 4 + 2] = pVx * rn;
            sndS[tid] = pS;
            rcvS[tid] = pR;
        }
        __syncthreads();

        // ---- Phase B: h = 0.018552463*silu(rad@W1), fast div, split bf16 ----
        {
            int e = tid >> 2;
            int j0 = (tid & 3) << 4;
            float hv[16];
#pragma unroll
            for (int i = 0; i < 16; i++) {
                float s = 0.f;
#pragma unroll
                for (int r = 0; r < 8; r++)
                    s += radS[e * 9 + r] * W1s[r * 64 + j0 + i];
                hv[i] = 0.018552463f * __fdividef(s, 1.f + __expf(-s));
            }
            u32 hi[8], lo[8];
#pragma unroll
            for (int q = 0; q < 8; q++) split2(hv[2 * q], hv[2 * q + 1], hi[q], lo[q]);
            int x = j0 >> 3;
            u32 o0 = swz(e, x, 128), o1 = swz(e, x + 1, 128);
            *(uint4*)(smem + OFF_H_HI + o0) = make_uint4(hi[0], hi[1], hi[2], hi[3]);
            *(uint4*)(smem + OFF_H_HI + o1) = make_uint4(hi[4], hi[5], hi[6], hi[7]);
            *(uint4*)(smem + OFF_H_LO + o0) = make_uint4(lo[0], lo[1], lo[2], lo[3]);
            *(uint4*)(smem + OFF_H_LO + o1) = make_uint4(lo[4], lo[5], lo[6], lo[7]);
        }
        __syncthreads();

        // ---- MMA C: R_n[128e,128c] = h @ W2^T, split-bf16 3-pass ----
        float accc[2][4][4];
#pragma unroll
        for (int a = 0; a < 2; a++)
#pragma unroll
            for (int b = 0; b < 4; b++)
#pragma unroll
                for (int c = 0; c < 4; c++) accc[a][b][c] = 0.f;
#pragma unroll
        for (int k = 0; k < 4; k++) {
            int g0 = 2 * k;
            u32 ah0[4], ah1[4], al0[4], al1[4];
            lda(ah0, sb + OFF_H_HI, wm * 32,      g0, lane, 128);
            lda(ah1, sb + OFF_H_HI, wm * 32 + 16, g0, lane, 128);
            lda(al0, sb + OFF_H_LO, wm * 32,      g0, lane, 128);
            lda(al1, sb + OFF_H_LO, wm * 32 + 16, g0, lane, 128);
#pragma unroll
            for (int np = 0; np < 2; np++) {
                u32 bh[4], bl[4];
                ldb(bh, sb + OFF_W2_HI, wn * 32 + np * 16, g0, lane, 128);
                ldb(bl, sb + OFF_W2_LO, wn * 32 + np * 16, g0, lane, 128);
                mma16816(accc[0][2 * np],     ah0, bh[0], bh[1]);
                mma16816(accc[0][2 * np + 1], ah0, bh[2], bh[3]);
                mma16816(accc[1][2 * np],     ah1, bh[0], bh[1]);
                mma16816(accc[1][2 * np + 1], ah1, bh[2], bh[3]);
                mma16816(accc[0][2 * np],     al0, bh[0], bh[1]);
                mma16816(accc[0][2 * np + 1], al0, bh[2], bh[3]);
                mma16816(accc[1][2 * np],     al1, bh[0], bh[1]);
                mma16816(accc[1][2 * np + 1], al1, bh[2], bh[3]);
                mma16816(accc[0][2 * np],     ah0, bl[0], bl[1]);
                mma16816(accc[0][2 * np + 1], ah0, bl[2], bl[3]);
                mma16816(accc[1][2 * np],     ah1, bl[0], bl[1]);
                mma16816(accc[1][2 * np + 1], ah1, bl[2], bl[3]);
            }
        }
        barg(gbar);   // wm-group: h rows [32wm,32wm+32) readers done

        // ---- readout C: gather + multiply + split + store (own wm rows) ----
#pragma unroll
        for (int mt = 0; mt < 2; mt++) {
            int r0 = wm * 32 + mt * 16 + gq;
            int r1 = r0 + 8;
            int s0 = sndS[r0], s1 = sndS[r1];
#pragma unroll
            for (int nt = 0; nt < 4; nt++) {
                int col = wn * 32 + nt * 8 + 2 * tq;
                float2 a0 = *(const float2*)&node_attrs[(u64)s0 * HID + col];
                float2 a1 = *(const float2*)&node_attrs[(u64)s1 * HID + col];
                float v00 = accc[mt][nt][0] * a0.x, v01 = accc[mt][nt][1] * a0.y;
                float v10 = accc[mt][nt][2] * a1.x, v11 = accc[mt][nt][3] * a1.y;
                u32 h0, l0, h1, l1;
                split2(v00, v01, h0, l0);
                split2(v10, v11, h1, l1);
                u32 o0 = swz(r0, col >> 3, 256) + (col & 7) * 2;
                u32 o1 = swz(r1, col >> 3, 256) + (col & 7) * 2;
                *(u32*)(smem + OFF_NF_HI + o0) = h0;
                *(u32*)(smem + OFF_NF_LO + o0) = l0;
                *(u32*)(smem + OFF_NF_HI + o1) = h1;
                *(u32*)(smem + OFF_NF_LO + o1) = l1;
            }
        }
        barg(gbar);   // wm-group: nf rows ready for MMA D

        float accd[2][6][4];
#pragma unroll
        for (int a = 0; a < 2; a++)
#pragma unroll
            for (int b = 0; b < 6; b++)
#pragma unroll
                for (int c = 0; c < 4; c++) accd[a][b][c] = 0.f;
        const int NB = wn * 48;
#pragma unroll
        for (int k = 0; k < 8; k++) {
            int g0 = 2 * k;
            u32 ah0[4], ah1[4], al0[4], al1[4];
            lda(ah0, sb + OFF_NF_HI, wm * 32,      g0, lane, 256);
            lda(ah1, sb + OFF_NF_HI, wm * 32 + 16, g0, lane, 256);
            lda(al0, sb + OFF_NF_LO, wm * 32,      g0, lane, 256);
            lda(al1, sb + OFF_NF_LO, wm * 32 + 16, g0, lane, 256);
#pragma unroll
            for (int np = 0; np < 3; np++) {
                u32 bh[4], bl[4];
                ldb(bh, sb + OFF_WC_HI, NB + np * 16, g0, lane, 256);
                ldb(bl, sb + OFF_WC_LO, NB + np * 16, g0, lane, 256);
                mma16816(accd[0][2 * np],     ah0, bh[0], bh[1]);
                mma16816(accd[0][2 * np + 1], ah0, bh[2], bh[3]);
                mma16816(accd[1][2 * np],     ah1, bh[0], bh[1]);
                mma16816(accd[1][2 * np + 1], ah1, bh[2], bh[3]);
                mma16816(accd[0][2 * np],     al0, bh[0], bh[1]);
                mma16816(accd[0][2 * np + 1], al0, bh[2], bh[3]);
                mma16816(accd[1][2 * np],     al1, bh[0], bh[1]);
                mma16816(accd[1][2 * np + 1], al1, bh[2], bh[3]);
                mma16816(accd[0][2 * np],     ah0, bl[0], bl[1]);
                mma16816(accd[0][2 * np + 1], ah0, bl[2], bl[3]);
                mma16816(accd[1][2 * np],     ah1, bl[0], bl[1]);
                mma16816(accd[1][2 * np + 1], ah1, bl[2], bl[3]);
            }
        }

        // ---- scatter: quad-pair merge via shfl -> red4 ----
#pragma unroll
        for (int mt = 0; mt < 2; mt++) {
            int r0 = wm * 32 + mt * 16 + gq;
            int r1 = r0 + 8;
            int myrow = (tq & 1) ? r1 : r0;
            float* gp = g_A + (u64)rcvS[myrow] * FEAT;
            float y0 = y1S[myrow * 4 + 0];
            float y1v = y1S[myrow * 4 + 1];
            float y2 = y1S[myrow * 4 + 2];
#pragma unroll
            for (int nt = 0; nt < 6; nt++) {
                u64 up0 = pack2(accd[mt][nt][0], accd[mt][nt][1]);
                u64 up1 = pack2(accd[mt][nt][2], accd[mt][nt][3]);
                u64 q0 = __shfl_xor_sync(0xffffffffu, up0, 1);
                u64 q1 = __shfl_xor_sync(0xffffffffu, up1, 1);
                float a0, a1, b0, b1;
                if ((tq & 1) == 0) {
                    unpack2(up0, a0, a1);
                    unpack2(q0, b0, b1);
                } else {
                    unpack2(q1, a0, a1);
                    unpack2(up1, b0, b1);
                }
                int colb = NB + nt * 8 + ((tq >> 1) << 2);
                if (colb < 128) {
                    red4(gp + colb, a0, a1, b0, b1);
                } else {
                    int m0 = colb - 128;
                    float* p = gp + 128 + m0 * 3;
                    float v0 = a0 * y0, v1 = a0 * y1v, v2 = a0 * y2;
                    float v3 = a1 * y0, v4 = a1 * y1v, v5 = a1 * y2;
                    float v6 = b0 * y0, v7 = b0 * y1v, v8 = b0 * y2;
                    float v9 = b1 * y0, v10 = b1 * y1v, v11 = b1 * y2;
                    if ((m0 & 2) == 0) {
                        red4(p, v0, v1, v2, v3);
                        red4(p + 4, v4, v5, v6, v7);
                        red4(p + 8, v8, v9, v10, v11);
                    } else {
                        red2(p, v0, v1);
                        red4(p + 2, v2, v3, v4, v5);
                        red4(p + 6, v6, v7, v8, v9);
                        red2(p + 10, v10, v11);
                    }
                }
            }
        }

        // ---- prefetch next tile's Phase-A inputs (overlaps barrier wait) ----
        {
            int nt2 = tile + gridDim.x;
            if (nt2 < ntiles) {
                pX = edge_len[nt2 * TEDGE + (tid >> 2)];
                if (tid < TEDGE) {
                    int e = nt2 * TEDGE + tid;
                    pVx = edge_vec[e * 3 + 0];
                    pVy = edge_vec[e * 3 + 1];
                    pVz = edge_vec[e * 3 + 2];
                    pS = edge_index[e];
                    pR = edge_index[NE + e];
                }
            }
        }
        __syncthreads();   // protect radS/y1S/snd/rcv for next tile
    }

    // ================= GRID BARRIER =================
    __threadfence();
    __syncthreads();
    if (tid == 0) {
        atomicAdd(&g_arrive, 1u);
        while (*(volatile unsigned int*)&g_arrive < (unsigned)gridDim.x)
            __nanosleep(128);
    }
    __syncthreads();
    __threadfence();

    // ================= NODE PHASE (split-bf16 HMMA) =================
    const float s_mix = 0.07216878364870323f;  // 1/sqrt(192)
    for (int i = tid; i < 128 * 192; i += NTHREADS) {
        int c = i / 192, k = i % 192;
        float v = Wmix0[k * 128 + c] * s_mix;
        u32 vu = __float_as_uint(v);
        u32 off = swz(c, k >> 3, 384) + (k & 7) * 2;
        *(unsigned short*)(smem + OFF_WM_HI + off) = (unsigned short)(vu >> 16);
        *(__nv_bfloat16*)(smem + OFF_WM_LO + off) =
            __float2bfloat16(v - __uint_as_float(vu & 0xFFFF0000u));
    }
    __syncthreads();

    const int ntilesN = (NN + TN - 1) / TN;  // 782
    for (int tile = blockIdx.x; tile < ntilesN; tile += gridDim.x) {
        const int nbase = tile * TN;

        // ---- build B0 split tiles [64n][192k] bf16 hi/lo ----
        {
            int n = tid >> 3;            // 0..63
            int k0 = (tid & 7) * 24;     // 24 consecutive k per thread
            int ng = nbase + n;
            float v[24];
            if (ng < NN) {
                const float* gp = g_A + (u64)ng * FEAT;
#pragma unroll
                for (int i = 0; i < 24; i++) {
                    int k = k0 + i;
                    if (k < 128) {
                        float a = gp[k];
                        v[i] = a * a;
                    } else {
                        int m = k - 128;
                        float q0 = gp[128 + m * 3], q1 = gp[128 + m * 3 + 1], q2 = gp[128 + m * 3 + 2];
                        v[i] = (q0 * q0 + q1 * q1 + q2 * q2) * 0.5773502691896258f;
                    }
                }
            } else {
#pragma unroll
                for (int i = 0; i < 24; i++) v[i] = 0.f;
            }
            u32 hi[12], lo[12];
#pragma unroll
            for (int q = 0; q < 12; q++) split2(v[2 * q], v[2 * q + 1], hi[q], lo[q]);
            int gbase = 3 * (tid & 7);
#pragma unroll
            for (int j = 0; j < 3; j++) {
                u32 off = swz(n, gbase + j, 384);
                *(uint4*)(smem + OFF_B0_HI + off) =
                    make_uint4(hi[4 * j], hi[4 * j + 1], hi[4 * j + 2], hi[4 * j + 3]);
                *(uint4*)(smem + OFF_B0_LO + off) =
                    make_uint4(lo[4 * j], lo[4 * j + 1], lo[4 * j + 2], lo[4 * j + 3]);
            }
        }
        __syncthreads();

        // ---- A1 copy to out + zero scratch cols 128..319 ----
        for (int idx = tid; idx < TN * 192; idx += NTHREADS) {
            int e = idx / 192, k = idx % 192;
            int n = nbase + e;
            if (n < NN) {
                u64 off = (u64)n * FEAT + 128 + k;
                out[off] = g_A[off];
                g_A[off] = 0.f;
            }
        }

        // ---- MMA: mix0[64n,128c] = B0 @ Wm^T, split-bf16 3-pass ----
        float acc[4][4];
#pragma unroll
        for (int b = 0; b < 4; b++)
#pragma unroll
            for (int c = 0; c < 4; c++) acc[b][c] = 0.f;
#pragma unroll
        for (int k = 0; k < 12; k++) {
            int g0 = 2 * k;
            u32 ah[4], al[4];
            lda(ah, sb + OFF_B0_HI, wm * 16, g0, lane, 384);
            lda(al, sb + OFF_B0_LO, wm * 16, g0, lane, 384);
#pragma unroll
            for (int np = 0; np < 2; np++) {
                u32 bh[4], bl[4];
                ldb(bh, sb + OFF_WM_HI, wn * 32 + np * 16, g0, lane, 384);
                ldb(bl, sb + OFF_WM_LO, wn * 32 + np * 16, g0, lane, 384);
                mma16816(acc[2 * np],     ah, bh[0], bh[1]);
                mma16816(acc[2 * np + 1], ah, bh[2], bh[3]);
                mma16816(acc[2 * np],     al, bh[0], bh[1]);
                mma16816(acc[2 * np + 1], al, bh[2], bh[3]);
                mma16816(acc[2 * np],     ah, bl[0], bl[1]);
                mma16816(acc[2 * np + 1], ah, bl[2], bl[3]);
            }
        }

        // ---- readout: out[:, :128] = A0 + mix0; zero scratch A0 ----
        {
            int row0 = nbase + wm * 16 + gq;
            int row1 = row0 + 8;
#pragma unroll
            for (int nt = 0; nt < 4; nt++) {
                int col = wn * 32 + nt * 8 + 2 * tq;
                if (row0 < NN) {
                    u64 off = (u64)row0 * FEAT + col;
                    float2 A0v = *(const float2*)&g_A[off];
                    *(float2*)&out[off] = make_float2(A0v.x + acc[nt][0], A0v.y + acc[nt][1]);
                    *(float2*)&g_A[off] = make_float2(0.f, 0.f);
                }
                if (row1 < NN) {
                    u64 off = (u64)row1 * FEAT + col;
                    float2 A0v = *(const float2*)&g_A[off];
                    *(float2*)&out[off] = make_float2(A0v.x + acc[nt][2], A0v.y + acc[nt][3]);
                    *(float2*)&g_A[off] = make_float2(0.f, 0.f);
                }
            }
        }
        __syncthreads();
    }

    // ---- reset barrier counters (last block out) ----
    __syncthreads();
    if (tid == 0) {
        __threadfence();
        unsigned d = atomicAdd(&g_depart, 1u);
        if (d == (unsigned)gridDim.x - 1) {
            g_arrive = 0;
            g_depart = 0;
            __threadfence();
        }
    }
}

extern "C" void kernel_launch(void* const* d_in, const int* in_sizes, int n_in,
                              void* d_out, int out_size) {
    const float* node_attrs = (const float*)d_in[0];
    const int*   edge_index = (const int*)d_in[1];
    const float* edge_vec   = (const float*)d_in[2];
    const float* edge_len   = (const float*)d_in[3];
    const float* W1         = (const float*)d_in[4];
    const float* W2         = (const float*)d_in[5];
    const float* Wtp0       = (const float*)d_in[6];
    const float* Wtp1       = (const float*)d_in[7];
    const float* Wmix0      = (const float*)d_in[8];
    float* out = (float*)d_out;

    cudaFuncSetAttribute(ace_fused_kernel, cudaFuncAttributeMaxDynamicSharedMemorySize, SMEM_BYTES);

    ace_fused_kernel<<<NBLOCKS, NTHREADS, SMEM_BYTES>>>(
        node_attrs, edge_index, edge_vec, edge_len, W1, W2, Wtp0, Wtp1, Wmix0, out);
}